// round 1
// baseline (speedup 1.0000x reference)
#include <cuda_runtime.h>
#include <cstdint>

#define TOK 8192
#define HD  2048
#define ID  1408
#define NE  8

#define BM 128
#define BN 64
#define BK 32
#define STAGES 3

// ---------------- device scratch (static: no allocations allowed) -------------
__device__ float g_xr[(size_t)TOK * HD];          //  67 MB tf32-rounded x
__device__ float g_wg[(size_t)NE * HD * ID];      //  92 MB tf32-rounded gate weights
__device__ float g_wu[(size_t)NE * HD * ID];      //  92 MB tf32-rounded up weights
__device__ float g_wd[(size_t)NE * ID * HD];      //  92 MB tf32-rounded down weights
__device__ int   g_cnt[NE];
__device__ int   g_tokl[NE * TOK];
__device__ float g_wtl[NE * TOK];
__device__ float g_h[(size_t)NE * TOK * ID];      // 369 MB intermediate activations

// ---------------- helpers ------------------------------------------------------
__device__ __forceinline__ float tf32_round(float x) {
    uint32_t u;
    asm("cvt.rna.tf32.f32 %0, %1;" : "=r"(u) : "f"(x));
    return __uint_as_float(u);
}
__device__ __forceinline__ uint32_t saddr(const void* p) {
    return (uint32_t)__cvta_generic_to_shared(p);
}
__device__ __forceinline__ void cp16(uint32_t dst, const void* src, int bytes) {
    asm volatile("cp.async.cg.shared.global [%0], [%1], 16, %2;"
                 :: "r"(dst), "l"(src), "r"(bytes));
}
__device__ __forceinline__ void cp_commit() { asm volatile("cp.async.commit_group;"); }
template <int N>
__device__ __forceinline__ void cp_wait() { asm volatile("cp.async.wait_group %0;" :: "n"(N)); }

__device__ __forceinline__ void mma_tf32(float d[4], const uint32_t a[4], const uint32_t b[2]) {
    asm volatile(
        "mma.sync.aligned.m16n8k8.row.col.f32.tf32.tf32.f32 "
        "{%0,%1,%2,%3}, {%4,%5,%6,%7}, {%8,%9}, {%0,%1,%2,%3};"
        : "+f"(d[0]), "+f"(d[1]), "+f"(d[2]), "+f"(d[3])
        : "r"(a[0]), "r"(a[1]), "r"(a[2]), "r"(a[3]), "r"(b[0]), "r"(b[1]));
}

// ---------------- small kernels ------------------------------------------------
__global__ void zero_cnt_kernel() {
    if (threadIdx.x < NE) g_cnt[threadIdx.x] = 0;
}

// which: 0->g_xr, 1->g_wg, 2->g_wu, 3->g_wd
__global__ void round_tf32_kernel(const float4* __restrict__ in, int which, int n4) {
    float4* out = which == 0 ? (float4*)g_xr :
                  which == 1 ? (float4*)g_wg :
                  which == 2 ? (float4*)g_wu : (float4*)g_wd;
    for (int i = blockIdx.x * blockDim.x + threadIdx.x; i < n4; i += gridDim.x * blockDim.x) {
        float4 v = in[i];
        v.x = tf32_round(v.x); v.y = tf32_round(v.y);
        v.z = tf32_round(v.z); v.w = tf32_round(v.w);
        out[i] = v;
    }
}

// Router: one warp per token. Softmax -> top2 -> renorm collapses to
// w0 = 1/(1+e), w1 = e/(1+e) with e = exp(l1 - l0).
__global__ void router_kernel(const float* __restrict__ x, const float* __restrict__ gw) {
    extern __shared__ float s_gw[];  // NE*HD floats = 64 KB
    for (int i = threadIdx.x; i < NE * HD; i += blockDim.x) s_gw[i] = gw[i];
    __syncthreads();

    int gtid = blockIdx.x * blockDim.x + threadIdx.x;
    int t = gtid >> 5;
    int lane = gtid & 31;
    if (t >= TOK) return;

    float acc[NE];
#pragma unroll
    for (int e = 0; e < NE; e++) acc[e] = 0.f;

    const float* xr = x + (size_t)t * HD;
    for (int i = lane; i < HD; i += 32) {
        float xv = xr[i];
#pragma unroll
        for (int e = 0; e < NE; e++) acc[e] += xv * s_gw[e * HD + i];
    }
#pragma unroll
    for (int e = 0; e < NE; e++) {
#pragma unroll
        for (int off = 16; off > 0; off >>= 1)
            acc[e] += __shfl_xor_sync(0xffffffffu, acc[e], off);
    }
    if (lane == 0) {
        int i0 = 0; float l0 = acc[0];
#pragma unroll
        for (int e = 1; e < NE; e++) if (acc[e] > l0) { l0 = acc[e]; i0 = e; }
        int i1 = -1; float l1 = -1e30f;
#pragma unroll
        for (int e = 0; e < NE; e++) if (e != i0 && acc[e] > l1) { l1 = acc[e]; i1 = e; }
        float ex = __expf(l1 - l0);
        float w0 = 1.f / (1.f + ex);
        float w1 = ex * w0;
        int s0 = atomicAdd(&g_cnt[i0], 1);
        g_tokl[i0 * TOK + s0] = t; g_wtl[i0 * TOK + s0] = w0;
        int s1 = atomicAdd(&g_cnt[i1], 1);
        g_tokl[i1 * TOK + s1] = t; g_wtl[i1 * TOK + s1] = w1;
    }
}

// ---------------- GEMM1: h = silu(x@Wg) * (x@Wu), gathered rows -----------------
struct SmemG1 {
    float A[STAGES][BM][BK + 4];
    float Bg[STAGES][BK][BN + 4];
    float Bu[STAGES][BK][BN + 4];
    int   tok[BM];
};

__device__ __forceinline__ void g1_load(SmemG1* s, int stage, int kt, int e,
                                        int m_base, int n_base, int cnt, int tid) {
    int k0 = kt * BK;
#pragma unroll
    for (int i = 0; i < 4; i++) {            // A tile: 128x32 floats = 1024 x 16B
        int c = tid + i * 256;
        int row = c >> 3;
        int col = (c & 7) << 2;
        int m = m_base + row;
        int tk = s->tok[row];
        const float* src = &g_xr[(size_t)tk * HD + k0 + col];
        cp16(saddr(&s->A[stage][row][col]), src, m < cnt ? 16 : 0);
    }
#pragma unroll
    for (int i = 0; i < 4; i++) {            // Bg + Bu: 2 x 32x64 floats = 1024 x 16B
        int c = tid + i * 256;
        int half = c >> 9;
        int cc = c & 511;
        int kr = cc >> 4;
        int col = (cc & 15) << 2;
        const float* base = half ? g_wu : g_wg;
        const float* src = &base[((size_t)e * HD + k0 + kr) * ID + n_base + col];
        float* dst = half ? &s->Bu[stage][kr][col] : &s->Bg[stage][kr][col];
        cp16(saddr(dst), src, 16);
    }
}

__global__ void __launch_bounds__(256) gemm1_kernel() {
    extern __shared__ __align__(16) char smem_raw[];
    SmemG1* s = (SmemG1*)smem_raw;

    int e = blockIdx.z;
    int cnt = g_cnt[e];
    int m_base = blockIdx.y * BM;
    if (m_base >= cnt) return;
    int n_base = blockIdx.x * BN;
    int tid = threadIdx.x;

    if (tid < BM) {
        int m = m_base + tid;
        s->tok[tid] = (m < cnt) ? g_tokl[e * TOK + m] : 0;
    }
    __syncthreads();

    int wid = tid >> 5, lane = tid & 31;
    int wm = wid >> 1, wn = wid & 1;
    int r = lane >> 2, cq = lane & 3;

    float acc_g[2][4][4], acc_u[2][4][4];
#pragma unroll
    for (int mf = 0; mf < 2; mf++)
#pragma unroll
        for (int nf = 0; nf < 4; nf++)
#pragma unroll
            for (int k = 0; k < 4; k++) { acc_g[mf][nf][k] = 0.f; acc_u[mf][nf][k] = 0.f; }

    const int kTiles = HD / BK;  // 64
#pragma unroll
    for (int st = 0; st < STAGES - 1; st++) {
        g1_load(s, st, st, e, m_base, n_base, cnt, tid);
        cp_commit();
    }

    for (int kt = 0; kt < kTiles; kt++) {
        cp_wait<STAGES - 2>();
        __syncthreads();                 // everyone done with stage kt-1 compute
        int nt = kt + STAGES - 1;
        if (nt < kTiles) g1_load(s, nt % STAGES, nt, e, m_base, n_base, cnt, tid);
        cp_commit();

        int sg = kt % STAGES;
#pragma unroll
        for (int kk = 0; kk < BK / 8; kk++) {
            int k8 = kk * 8;
            uint32_t a[2][4];
#pragma unroll
            for (int mf = 0; mf < 2; mf++) {
                int row = wm * 32 + mf * 16;
                a[mf][0] = __float_as_uint(s->A[sg][row + r][k8 + cq]);
                a[mf][1] = __float_as_uint(s->A[sg][row + r + 8][k8 + cq]);
                a[mf][2] = __float_as_uint(s->A[sg][row + r][k8 + cq + 4]);
                a[mf][3] = __float_as_uint(s->A[sg][row + r + 8][k8 + cq + 4]);
            }
            uint32_t bg[4][2], bu[4][2];
#pragma unroll
            for (int nf = 0; nf < 4; nf++) {
                int coln = wn * 32 + nf * 8 + r;
                bg[nf][0] = __float_as_uint(s->Bg[sg][k8 + cq][coln]);
                bg[nf][1] = __float_as_uint(s->Bg[sg][k8 + cq + 4][coln]);
                bu[nf][0] = __float_as_uint(s->Bu[sg][k8 + cq][coln]);
                bu[nf][1] = __float_as_uint(s->Bu[sg][k8 + cq + 4][coln]);
            }
#pragma unroll
            for (int mf = 0; mf < 2; mf++)
#pragma unroll
                for (int nf = 0; nf < 4; nf++) {
                    mma_tf32(acc_g[mf][nf], a[mf], bg[nf]);
                    mma_tf32(acc_u[mf][nf], a[mf], bu[nf]);
                }
        }
    }

    // epilogue: silu(g)*u, round to tf32, store to h
#pragma unroll
    for (int mf = 0; mf < 2; mf++) {
#pragma unroll
        for (int nf = 0; nf < 4; nf++) {
            int row0 = m_base + wm * 32 + mf * 16 + r;
            int col = n_base + wn * 32 + nf * 8 + cq * 2;
            if (row0 < cnt) {
                float g0 = acc_g[mf][nf][0], u0 = acc_u[mf][nf][0];
                float g1 = acc_g[mf][nf][1], u1 = acc_u[mf][nf][1];
                float v0 = (g0 / (1.f + __expf(-g0))) * u0;
                float v1 = (g1 / (1.f + __expf(-g1))) * u1;
                float2* p = (float2*)&g_h[((size_t)e * TOK + row0) * ID + col];
                *p = make_float2(tf32_round(v0), tf32_round(v1));
            }
            int row1 = row0 + 8;
            if (row1 < cnt) {
                float g0 = acc_g[mf][nf][2], u0 = acc_u[mf][nf][2];
                float g1 = acc_g[mf][nf][3], u1 = acc_u[mf][nf][3];
                float v0 = (g0 / (1.f + __expf(-g0))) * u0;
                float v1 = (g1 / (1.f + __expf(-g1))) * u1;
                float2* p = (float2*)&g_h[((size_t)e * TOK + row1) * ID + col];
                *p = make_float2(tf32_round(v0), tf32_round(v1));
            }
        }
    }
}

// ---------------- GEMM2: out[tok] += w * (h @ Wd) -------------------------------
struct SmemG2 {
    float A[STAGES][BM][BK + 4];
    float B[STAGES][BK][BN + 4];
    int   tok[BM];
    float wt[BM];
};

__device__ __forceinline__ void g2_load(SmemG2* s, int stage, int kt, int e,
                                        int m_base, int n_base, int cnt, int tid) {
    int k0 = kt * BK;
#pragma unroll
    for (int i = 0; i < 4; i++) {
        int c = tid + i * 256;
        int row = c >> 3;
        int col = (c & 7) << 2;
        int m = m_base + row;
        const float* src = &g_h[((size_t)e * TOK + m) * ID + k0 + col];
        cp16(saddr(&s->A[stage][row][col]), src, m < cnt ? 16 : 0);
    }
#pragma unroll
    for (int i = 0; i < 2; i++) {
        int c = tid + i * 256;
        int kr = c >> 4;
        int col = (c & 15) << 2;
        const float* src = &g_wd[((size_t)e * ID + k0 + kr) * HD + n_base + col];
        cp16(saddr(&s->B[stage][kr][col]), src, 16);
    }
}

__global__ void __launch_bounds__(256) gemm2_kernel(float* __restrict__ out) {
    extern __shared__ __align__(16) char smem_raw[];
    SmemG2* s = (SmemG2*)smem_raw;

    int e = blockIdx.z;
    int cnt = g_cnt[e];
    int m_base = blockIdx.y * BM;
    if (m_base >= cnt) return;
    int n_base = blockIdx.x * BN;
    int tid = threadIdx.x;

    if (tid < BM) {
        int m = m_base + tid;
        if (m < cnt) { s->tok[tid] = g_tokl[e * TOK + m]; s->wt[tid] = g_wtl[e * TOK + m]; }
        else         { s->tok[tid] = 0;                   s->wt[tid] = 0.f; }
    }
    __syncthreads();

    int wid = tid >> 5, lane = tid & 31;
    int wm = wid >> 1, wn = wid & 1;
    int r = lane >> 2, cq = lane & 3;

    float acc[2][4][4];
#pragma unroll
    for (int mf = 0; mf < 2; mf++)
#pragma unroll
        for (int nf = 0; nf < 4; nf++)
#pragma unroll
            for (int k = 0; k < 4; k++) acc[mf][nf][k] = 0.f;

    const int kTiles = ID / BK;  // 44
#pragma unroll
    for (int st = 0; st < STAGES - 1; st++) {
        g2_load(s, st, st, e, m_base, n_base, cnt, tid);
        cp_commit();
    }

    for (int kt = 0; kt < kTiles; kt++) {
        cp_wait<STAGES - 2>();
        __syncthreads();
        int nt = kt + STAGES - 1;
        if (nt < kTiles) g2_load(s, nt % STAGES, nt, e, m_base, n_base, cnt, tid);
        cp_commit();

        int sg = kt % STAGES;
#pragma unroll
        for (int kk = 0; kk < BK / 8; kk++) {
            int k8 = kk * 8;
            uint32_t a[2][4];
#pragma unroll
            for (int mf = 0; mf < 2; mf++) {
                int row = wm * 32 + mf * 16;
                a[mf][0] = __float_as_uint(s->A[sg][row + r][k8 + cq]);
                a[mf][1] = __float_as_uint(s->A[sg][row + r + 8][k8 + cq]);
                a[mf][2] = __float_as_uint(s->A[sg][row + r][k8 + cq + 4]);
                a[mf][3] = __float_as_uint(s->A[sg][row + r + 8][k8 + cq + 4]);
            }
            uint32_t b[4][2];
#pragma unroll
            for (int nf = 0; nf < 4; nf++) {
                int coln = wn * 32 + nf * 8 + r;
                b[nf][0] = __float_as_uint(s->B[sg][k8 + cq][coln]);
                b[nf][1] = __float_as_uint(s->B[sg][k8 + cq + 4][coln]);
            }
#pragma unroll
            for (int mf = 0; mf < 2; mf++)
#pragma unroll
                for (int nf = 0; nf < 4; nf++)
                    mma_tf32(acc[mf][nf], a[mf], b[nf]);
        }
    }

    // epilogue: weighted scatter-add into out
#pragma unroll
    for (int mf = 0; mf < 2; mf++) {
#pragma unroll
        for (int nf = 0; nf < 4; nf++) {
            int rl0 = wm * 32 + mf * 16 + r;
            int col = n_base + wn * 32 + nf * 8 + cq * 2;
            if (m_base + rl0 < cnt) {
                int t = s->tok[rl0];
                float w = s->wt[rl0];
                size_t o = (size_t)t * HD + col;
                atomicAdd(&out[o],     w * acc[mf][nf][0]);
                atomicAdd(&out[o + 1], w * acc[mf][nf][1]);
            }
            int rl1 = rl0 + 8;
            if (m_base + rl1 < cnt) {
                int t = s->tok[rl1];
                float w = s->wt[rl1];
                size_t o = (size_t)t * HD + col;
                atomicAdd(&out[o],     w * acc[mf][nf][2]);
                atomicAdd(&out[o + 1], w * acc[mf][nf][3]);
            }
        }
    }
}

// ---------------- host launcher -------------------------------------------------
extern "C" void kernel_launch(void* const* d_in, const int* in_sizes, int n_in,
                              void* d_out, int out_size) {
    const float* x  = (const float*)d_in[0];
    const float* gw = (const float*)d_in[1];
    const float* wg = (const float*)d_in[2];
    const float* wu = (const float*)d_in[3];
    const float* wd = (const float*)d_in[4];
    float* out = (float*)d_out;
    (void)in_sizes; (void)n_in;

    cudaMemsetAsync(d_out, 0, (size_t)out_size * sizeof(float));

    zero_cnt_kernel<<<1, 32>>>();

    round_tf32_kernel<<<2048, 256>>>((const float4*)x,  0, TOK * HD / 4);
    round_tf32_kernel<<<2048, 256>>>((const float4*)wg, 1, NE * HD * ID / 4);
    round_tf32_kernel<<<2048, 256>>>((const float4*)wu, 2, NE * HD * ID / 4);
    round_tf32_kernel<<<2048, 256>>>((const float4*)wd, 3, NE * ID * HD / 4);

    cudaFuncSetAttribute(router_kernel, cudaFuncAttributeMaxDynamicSharedMemorySize,
                         NE * HD * (int)sizeof(float));
    router_kernel<<<TOK * 32 / 256, 256, NE * HD * sizeof(float)>>>(x, gw);

    cudaFuncSetAttribute(gemm1_kernel, cudaFuncAttributeMaxDynamicSharedMemorySize,
                         (int)sizeof(SmemG1));
    dim3 grid1(ID / BN, TOK / BM, NE);
    gemm1_kernel<<<grid1, 256, sizeof(SmemG1)>>>();

    cudaFuncSetAttribute(gemm2_kernel, cudaFuncAttributeMaxDynamicSharedMemorySize,
                         (int)sizeof(SmemG2));
    dim3 grid2(HD / BN, TOK / BM, NE);
    gemm2_kernel<<<grid2, 256, sizeof(SmemG2)>>>(out);
}

// round 3
// speedup vs baseline: 1.1500x; 1.1500x over previous
#include <cuda_runtime.h>
#include <cstdint>

#define TOK 8192
#define HD  2048
#define ID  1408
#define NE  8

#define BM 128
#define BN 128
#define BK 32
#define A_ST 36      // 32 + 4 pad (floats)
#define B_ST 136     // 128 + 8 pad (floats)

// ---------------- device scratch (no allocations allowed) ----------------------
__device__ float g_xr[(size_t)TOK * HD];        // tf32-rounded x  [T][H]
__device__ float g_wg[(size_t)NE * HD * ID];    // tf32-rounded, native [H][I] = [k][n]
__device__ float g_wu[(size_t)NE * HD * ID];
__device__ float g_wd[(size_t)NE * ID * HD];    // native [I][H] = [k][n]
__device__ int   g_cnt[NE];
__device__ int   g_tokl[NE * TOK];
__device__ float g_wtl[NE * TOK];
__device__ float g_h[(size_t)NE * TOK * ID];    // intermediate (slot-indexed)

// ---------------- helpers ------------------------------------------------------
__device__ __forceinline__ float tf32_round(float x) {
    uint32_t u;
    asm("cvt.rna.tf32.f32 %0, %1;" : "=r"(u) : "f"(x));
    return __uint_as_float(u);
}
__device__ __forceinline__ uint32_t saddr(const void* p) {
    return (uint32_t)__cvta_generic_to_shared(p);
}
__device__ __forceinline__ void cp16(uint32_t dst, const void* src) {
    asm volatile("cp.async.cg.shared.global [%0], [%1], 16;" :: "r"(dst), "l"(src));
}
__device__ __forceinline__ void cp_commit() { asm volatile("cp.async.commit_group;"); }
template <int N>
__device__ __forceinline__ void cp_wait() { asm volatile("cp.async.wait_group %0;" :: "n"(N)); }

__device__ __forceinline__ void mma_tf32(float d[4], const uint32_t a[4], const uint32_t b[2]) {
    asm volatile(
        "mma.sync.aligned.m16n8k8.row.col.f32.tf32.tf32.f32 "
        "{%0,%1,%2,%3}, {%4,%5,%6,%7}, {%8,%9}, {%0,%1,%2,%3};"
        : "+f"(d[0]), "+f"(d[1]), "+f"(d[2]), "+f"(d[3])
        : "r"(a[0]), "r"(a[1]), "r"(a[2]), "r"(a[3]), "r"(b[0]), "r"(b[1]));
}

// ---------------- small kernels ------------------------------------------------
__global__ void zero_cnt_kernel() {
    if (threadIdx.x < NE) g_cnt[threadIdx.x] = 0;
}

// which: 1->g_wg, 2->g_wu, 3->g_wd  (straight round, no transpose)
__global__ void round_tf32_kernel(const float4* __restrict__ in, int which, int n4) {
    float4* out = which == 1 ? (float4*)g_wg :
                  which == 2 ? (float4*)g_wu : (float4*)g_wd;
    for (int i = blockIdx.x * blockDim.x + threadIdx.x; i < n4; i += gridDim.x * blockDim.x) {
        float4 v = in[i];
        v.x = tf32_round(v.x); v.y = tf32_round(v.y);
        v.z = tf32_round(v.z); v.w = tf32_round(v.w);
        out[i] = v;
    }
}

// Router + fused tf32 rounding of x into g_xr. One warp per token.
__global__ void router_kernel(const float* __restrict__ x, const float* __restrict__ gw) {
    extern __shared__ float s_gw[];  // NE*HD = 64 KB
    for (int i = threadIdx.x; i < NE * HD; i += blockDim.x) s_gw[i] = gw[i];
    __syncthreads();

    int gtid = blockIdx.x * blockDim.x + threadIdx.x;
    int t = gtid >> 5, lane = gtid & 31;
    if (t >= TOK) return;

    float acc[NE];
#pragma unroll
    for (int e = 0; e < NE; e++) acc[e] = 0.f;

    const float* xr = x + (size_t)t * HD;
    float* xo = g_xr + (size_t)t * HD;
    for (int i = lane; i < HD; i += 32) {
        float xv = xr[i];
        xo[i] = tf32_round(xv);
#pragma unroll
        for (int e = 0; e < NE; e++) acc[e] += xv * s_gw[e * HD + i];
    }
#pragma unroll
    for (int e = 0; e < NE; e++) {
#pragma unroll
        for (int off = 16; off > 0; off >>= 1)
            acc[e] += __shfl_xor_sync(0xffffffffu, acc[e], off);
    }
    if (lane == 0) {
        int i0 = 0; float l0 = acc[0];
#pragma unroll
        for (int e = 1; e < NE; e++) if (acc[e] > l0) { l0 = acc[e]; i0 = e; }
        int i1 = -1; float l1 = -1e30f;
#pragma unroll
        for (int e = 0; e < NE; e++) if (e != i0 && acc[e] > l1) { l1 = acc[e]; i1 = e; }
        float ex = __expf(l1 - l0);
        float w0 = 1.f / (1.f + ex);
        float w1 = ex * w0;
        int s0 = atomicAdd(&g_cnt[i0], 1);
        g_tokl[i0 * TOK + s0] = t; g_wtl[i0 * TOK + s0] = w0;
        int s1 = atomicAdd(&g_cnt[i1], 1);
        g_tokl[i1 * TOK + s1] = t; g_wtl[i1 * TOK + s1] = w1;
    }
}

// ---------------- GEMM1: h = silu(x@Wg) * (x@Wu), block 128x128, warp 64x32 -----
struct SmemG1 {
    float A[2][BM][A_ST];
    float Bg[2][BK][B_ST];
    float Bu[2][BK][B_ST];
    int   tok[BM];
};

__device__ __forceinline__ void g1_load(SmemG1* s, int st, int k0,
                                        const int* tok_s, int e, int n_base, int tid) {
#pragma unroll
    for (int i = 0; i < 4; i++) {                 // A: 128x32 = 1024 x 16B
        int idx = tid + i * 256;
        int row = idx >> 3, c = idx & 7;
        cp16(saddr(&s->A[st][row][c * 4]), &g_xr[(size_t)tok_s[row] * HD + k0 + c * 4]);
    }
    const float* bg = g_wg + ((size_t)e * HD + k0) * ID + n_base;
    const float* bu = g_wu + ((size_t)e * HD + k0) * ID + n_base;
#pragma unroll
    for (int i = 0; i < 4; i++) {                 // Bg: 32x128 = 1024 x 16B
        int idx = tid + i * 256;
        int kr = idx >> 5, c = idx & 31;
        cp16(saddr(&s->Bg[st][kr][c * 4]), bg + (size_t)kr * ID + c * 4);
        cp16(saddr(&s->Bu[st][kr][c * 4]), bu + (size_t)kr * ID + c * 4);
    }
}

#define KT1 (HD / BK)   // 64

__global__ void __launch_bounds__(256, 1) gemm1_kernel() {
    extern __shared__ __align__(16) char smem_raw[];
    SmemG1* s = (SmemG1*)smem_raw;

    int e = blockIdx.z;
    int cnt = g_cnt[e];
    int m_base = blockIdx.y * BM;
    if (m_base >= cnt) return;
    int n_base = blockIdx.x * BN;
    int tid = threadIdx.x;

    if (tid < BM) {
        int m = m_base + tid;
        s->tok[tid] = (m < cnt) ? g_tokl[e * TOK + m] : 0;
    }
    __syncthreads();

    int wid = tid >> 5, lane = tid & 31;
    int wm = wid >> 2, wn = wid & 3;              // 2 x 4 warps
    int r = lane >> 2, cq = lane & 3;

    float acc_g[4][4][4], acc_u[4][4][4];
#pragma unroll
    for (int mf = 0; mf < 4; mf++)
#pragma unroll
        for (int nf = 0; nf < 4; nf++)
#pragma unroll
            for (int k = 0; k < 4; k++) { acc_g[mf][nf][k] = 0.f; acc_u[mf][nf][k] = 0.f; }

    g1_load(s, 0, 0, s->tok, e, n_base, tid);
    cp_commit();

    for (int kt = 0; kt < KT1; kt++) {
        if (kt + 1 < KT1) {
            g1_load(s, (kt + 1) & 1, (kt + 1) * BK, s->tok, e, n_base, tid);
            cp_commit();
            cp_wait<1>();
        } else {
            cp_wait<0>();
        }
        __syncthreads();

        int sg = kt & 1;
#pragma unroll
        for (int kk = 0; kk < BK / 8; kk++) {
            int k8 = kk * 8;
            uint32_t a[4][4];
#pragma unroll
            for (int mf = 0; mf < 4; mf++) {
                int row = wm * 64 + mf * 16;
                a[mf][0] = __float_as_uint(s->A[sg][row + r][k8 + cq]);
                a[mf][1] = __float_as_uint(s->A[sg][row + r + 8][k8 + cq]);
                a[mf][2] = __float_as_uint(s->A[sg][row + r][k8 + cq + 4]);
                a[mf][3] = __float_as_uint(s->A[sg][row + r + 8][k8 + cq + 4]);
            }
            uint32_t bg[4][2], bu[4][2];
#pragma unroll
            for (int nf = 0; nf < 4; nf++) {
                int coln = wn * 32 + nf * 8 + r;
                bg[nf][0] = __float_as_uint(s->Bg[sg][k8 + cq][coln]);
                bg[nf][1] = __float_as_uint(s->Bg[sg][k8 + cq + 4][coln]);
                bu[nf][0] = __float_as_uint(s->Bu[sg][k8 + cq][coln]);
                bu[nf][1] = __float_as_uint(s->Bu[sg][k8 + cq + 4][coln]);
            }
#pragma unroll
            for (int mf = 0; mf < 4; mf++)
#pragma unroll
                for (int nf = 0; nf < 4; nf++) {
                    mma_tf32(acc_g[mf][nf], a[mf], bg[nf]);
                    mma_tf32(acc_u[mf][nf], a[mf], bu[nf]);
                }
        }
        __syncthreads();
    }

    // epilogue: silu(g)*u -> tf32 round -> g_h
#pragma unroll
    for (int mf = 0; mf < 4; mf++) {
#pragma unroll
        for (int nf = 0; nf < 4; nf++) {
            int rl = wm * 64 + mf * 16 + r;
            int col = n_base + wn * 32 + nf * 8 + cq * 2;
            if (m_base + rl < cnt) {
                float g0 = acc_g[mf][nf][0], u0 = acc_u[mf][nf][0];
                float g1 = acc_g[mf][nf][1], u1 = acc_u[mf][nf][1];
                float v0 = (g0 / (1.f + __expf(-g0))) * u0;
                float v1 = (g1 / (1.f + __expf(-g1))) * u1;
                float2* p = (float2*)&g_h[((size_t)e * TOK + m_base + rl) * ID + col];
                *p = make_float2(tf32_round(v0), tf32_round(v1));
            }
            if (m_base + rl + 8 < cnt) {
                float g0 = acc_g[mf][nf][2], u0 = acc_u[mf][nf][2];
                float g1 = acc_g[mf][nf][3], u1 = acc_u[mf][nf][3];
                float v0 = (g0 / (1.f + __expf(-g0))) * u0;
                float v1 = (g1 / (1.f + __expf(-g1))) * u1;
                float2* p = (float2*)&g_h[((size_t)e * TOK + m_base + rl + 8) * ID + col];
                *p = make_float2(tf32_round(v0), tf32_round(v1));
            }
        }
    }
}

// ---------------- GEMM2: out[tok] += w * (h @ Wd), block 128x128, warp 64x32 ----
struct SmemG2 {
    float A[2][BM][A_ST];
    float B[2][BK][B_ST];
    int   tok[BM];
    float wt[BM];
};

__device__ __forceinline__ void g2_load(SmemG2* s, int st, int k0,
                                        int e, int m_base, int n_base, int tid) {
    const float* arow = g_h + ((size_t)e * TOK + m_base) * ID + k0;
    const float* brow = g_wd + ((size_t)e * ID + k0) * HD + n_base;
#pragma unroll
    for (int i = 0; i < 4; i++) {
        int idx = tid + i * 256;
        int row = idx >> 3, c = idx & 7;
        cp16(saddr(&s->A[st][row][c * 4]), arow + (size_t)row * ID + c * 4);
    }
#pragma unroll
    for (int i = 0; i < 4; i++) {
        int idx = tid + i * 256;
        int kr = idx >> 5, c = idx & 31;
        cp16(saddr(&s->B[st][kr][c * 4]), brow + (size_t)kr * HD + c * 4);
    }
}

#define KT2 (ID / BK)   // 44

__global__ void __launch_bounds__(256, 2) gemm2_kernel(float* __restrict__ out) {
    extern __shared__ __align__(16) char smem_raw[];
    SmemG2* s = (SmemG2*)smem_raw;

    int e = blockIdx.z;
    int cnt = g_cnt[e];
    int m_base = blockIdx.y * BM;
    if (m_base >= cnt) return;
    int n_base = blockIdx.x * BN;
    int tid = threadIdx.x;

    if (tid < BM) {
        int m = m_base + tid;
        if (m < cnt) { s->tok[tid] = g_tokl[e * TOK + m]; s->wt[tid] = g_wtl[e * TOK + m]; }
        else         { s->tok[tid] = 0;                   s->wt[tid] = 0.f; }
    }
    __syncthreads();

    int wid = tid >> 5, lane = tid & 31;
    int wm = wid >> 2, wn = wid & 3;
    int r = lane >> 2, cq = lane & 3;

    float acc[4][4][4];
#pragma unroll
    for (int mf = 0; mf < 4; mf++)
#pragma unroll
        for (int nf = 0; nf < 4; nf++)
#pragma unroll
            for (int k = 0; k < 4; k++) acc[mf][nf][k] = 0.f;

    g2_load(s, 0, 0, e, m_base, n_base, tid);
    cp_commit();

    for (int kt = 0; kt < KT2; kt++) {
        if (kt + 1 < KT2) {
            g2_load(s, (kt + 1) & 1, (kt + 1) * BK, e, m_base, n_base, tid);
            cp_commit();
            cp_wait<1>();
        } else {
            cp_wait<0>();
        }
        __syncthreads();

        int sg = kt & 1;
#pragma unroll
        for (int kk = 0; kk < BK / 8; kk++) {
            int k8 = kk * 8;
            uint32_t a[4][4];
#pragma unroll
            for (int mf = 0; mf < 4; mf++) {
                int row = wm * 64 + mf * 16;
                a[mf][0] = __float_as_uint(s->A[sg][row + r][k8 + cq]);
                a[mf][1] = __float_as_uint(s->A[sg][row + r + 8][k8 + cq]);
                a[mf][2] = __float_as_uint(s->A[sg][row + r][k8 + cq + 4]);
                a[mf][3] = __float_as_uint(s->A[sg][row + r + 8][k8 + cq + 4]);
            }
            uint32_t b[4][2];
#pragma unroll
            for (int nf = 0; nf < 4; nf++) {
                int coln = wn * 32 + nf * 8 + r;
                b[nf][0] = __float_as_uint(s->B[sg][k8 + cq][coln]);
                b[nf][1] = __float_as_uint(s->B[sg][k8 + cq + 4][coln]);
            }
#pragma unroll
            for (int mf = 0; mf < 4; mf++)
#pragma unroll
                for (int nf = 0; nf < 4; nf++)
                    mma_tf32(acc[mf][nf], a[mf], b[nf]);
        }
        __syncthreads();
    }

    // epilogue: weighted scatter-add
#pragma unroll
    for (int mf = 0; mf < 4; mf++) {
#pragma unroll
        for (int nf = 0; nf < 4; nf++) {
            int rl = wm * 64 + mf * 16 + r;
            int col = n_base + wn * 32 + nf * 8 + cq * 2;
            if (m_base + rl < cnt) {
                int t = s->tok[rl];
                float w = s->wt[rl];
                size_t o = (size_t)t * HD + col;
                atomicAdd(&out[o],     w * acc[mf][nf][0]);
                atomicAdd(&out[o + 1], w * acc[mf][nf][1]);
            }
            if (m_base + rl + 8 < cnt) {
                int t = s->tok[rl + 8];
                float w = s->wt[rl + 8];
                size_t o = (size_t)t * HD + col;
                atomicAdd(&out[o],     w * acc[mf][nf][2]);
                atomicAdd(&out[o + 1], w * acc[mf][nf][3]);
            }
        }
    }
}

// ---------------- host launcher -------------------------------------------------
extern "C" void kernel_launch(void* const* d_in, const int* in_sizes, int n_in,
                              void* d_out, int out_size) {
    const float* x  = (const float*)d_in[0];
    const float* gw = (const float*)d_in[1];
    const float* wg = (const float*)d_in[2];
    const float* wu = (const float*)d_in[3];
    const float* wd = (const float*)d_in[4];
    float* out = (float*)d_out;
    (void)in_sizes; (void)n_in;

    cudaMemsetAsync(d_out, 0, (size_t)out_size * sizeof(float));
    zero_cnt_kernel<<<1, 32>>>();

    round_tf32_kernel<<<2048, 256>>>((const float4*)wg, 1, NE * HD * ID / 4);
    round_tf32_kernel<<<2048, 256>>>((const float4*)wu, 2, NE * HD * ID / 4);
    round_tf32_kernel<<<2048, 256>>>((const float4*)wd, 3, NE * ID * HD / 4);

    cudaFuncSetAttribute(router_kernel, cudaFuncAttributeMaxDynamicSharedMemorySize,
                         NE * HD * (int)sizeof(float));
    router_kernel<<<TOK * 32 / 256, 256, NE * HD * sizeof(float)>>>(x, gw);

    cudaFuncSetAttribute(gemm1_kernel, cudaFuncAttributeMaxDynamicSharedMemorySize,
                         (int)sizeof(SmemG1));
    dim3 grid1(ID / BN, TOK / BM, NE);     // 11 x 64 x 8
    gemm1_kernel<<<grid1, 256, sizeof(SmemG1)>>>();

    cudaFuncSetAttribute(gemm2_kernel, cudaFuncAttributeMaxDynamicSharedMemorySize,
                         (int)sizeof(SmemG2));
    dim3 grid2(HD / BN, TOK / BM, NE);     // 16 x 64 x 8
    gemm2_kernel<<<grid2, 256, sizeof(SmemG2)>>>(out);
}

// round 4
// speedup vs baseline: 1.2301x; 1.0697x over previous
#include <cuda_runtime.h>
#include <cstdint>

#define TOK 8192
#define HD  2048
#define ID  1408
#define NE  8

#define BM  128
#define BK  32
#define BN1 64       // gemm1 n-tile
#define BN2 128      // gemm2 n-tile
#define A_ST 36      // 32 + 4 pad
#define B1_ST 72     // 64 + 8 pad
#define B2_ST 136    // 128 + 8 pad

// ---------------- device scratch (no allocations allowed) ----------------------
__device__ float g_xr[(size_t)TOK * HD];        // tf32-rounded x
__device__ float g_wg[(size_t)NE * HD * ID];    // tf32-rounded, native [k][n]
__device__ float g_wu[(size_t)NE * HD * ID];
__device__ float g_wd[(size_t)NE * ID * HD];
__device__ int   g_cnt[NE];
__device__ int   g_tokp[NE * TOK];              // token | (k<<31)
__device__ float g_w2[TOK * 2];                 // per-token (w0, w1)
__device__ float g_h[(size_t)NE * TOK * ID];    // intermediate (slot-indexed)
__device__ float g_y[(size_t)2 * TOK * HD];     // unweighted expert outputs per k

// ---------------- helpers ------------------------------------------------------
__device__ __forceinline__ float tf32_round(float x) {
    uint32_t u;
    asm("cvt.rna.tf32.f32 %0, %1;" : "=r"(u) : "f"(x));
    return __uint_as_float(u);
}
__device__ __forceinline__ uint32_t saddr(const void* p) {
    return (uint32_t)__cvta_generic_to_shared(p);
}
__device__ __forceinline__ void cp16(uint32_t dst, const void* src) {
    asm volatile("cp.async.cg.shared.global [%0], [%1], 16;" :: "r"(dst), "l"(src));
}
__device__ __forceinline__ void cp_commit() { asm volatile("cp.async.commit_group;"); }
template <int N>
__device__ __forceinline__ void cp_wait() { asm volatile("cp.async.wait_group %0;" :: "n"(N)); }

__device__ __forceinline__ void mma_tf32(float d[4], const uint32_t a[4], const uint32_t b[2]) {
    asm volatile(
        "mma.sync.aligned.m16n8k8.row.col.f32.tf32.tf32.f32 "
        "{%0,%1,%2,%3}, {%4,%5,%6,%7}, {%8,%9}, {%0,%1,%2,%3};"
        : "+f"(d[0]), "+f"(d[1]), "+f"(d[2]), "+f"(d[3])
        : "r"(a[0]), "r"(a[1]), "r"(a[2]), "r"(a[3]), "r"(b[0]), "r"(b[1]));
}

// ---------------- small kernels ------------------------------------------------
__global__ void zero_cnt_kernel() {
    if (threadIdx.x < NE) g_cnt[threadIdx.x] = 0;
}

__global__ void round_tf32_kernel(const float4* __restrict__ in, int which, int n4) {
    float4* out = which == 1 ? (float4*)g_wg :
                  which == 2 ? (float4*)g_wu : (float4*)g_wd;
    for (int i = blockIdx.x * blockDim.x + threadIdx.x; i < n4; i += gridDim.x * blockDim.x) {
        float4 v = in[i];
        v.x = tf32_round(v.x); v.y = tf32_round(v.y);
        v.z = tf32_round(v.z); v.w = tf32_round(v.w);
        out[i] = v;
    }
}

// Router + fused tf32 rounding of x. One warp per token.
__global__ void router_kernel(const float* __restrict__ x, const float* __restrict__ gw) {
    extern __shared__ float s_gw[];  // NE*HD = 64 KB
    for (int i = threadIdx.x; i < NE * HD; i += blockDim.x) s_gw[i] = gw[i];
    __syncthreads();

    int gtid = blockIdx.x * blockDim.x + threadIdx.x;
    int t = gtid >> 5, lane = gtid & 31;
    if (t >= TOK) return;

    float acc[NE];
#pragma unroll
    for (int e = 0; e < NE; e++) acc[e] = 0.f;

    const float* xr = x + (size_t)t * HD;
    float* xo = g_xr + (size_t)t * HD;
    for (int i = lane; i < HD; i += 32) {
        float xv = xr[i];
        xo[i] = tf32_round(xv);
#pragma unroll
        for (int e = 0; e < NE; e++) acc[e] += xv * s_gw[e * HD + i];
    }
#pragma unroll
    for (int e = 0; e < NE; e++) {
#pragma unroll
        for (int off = 16; off > 0; off >>= 1)
            acc[e] += __shfl_xor_sync(0xffffffffu, acc[e], off);
    }
    if (lane == 0) {
        int i0 = 0; float l0 = acc[0];
#pragma unroll
        for (int e = 1; e < NE; e++) if (acc[e] > l0) { l0 = acc[e]; i0 = e; }
        int i1 = -1; float l1 = -1e30f;
#pragma unroll
        for (int e = 0; e < NE; e++) if (e != i0 && acc[e] > l1) { l1 = acc[e]; i1 = e; }
        float ex = __expf(l1 - l0);
        float w0 = 1.f / (1.f + ex);
        float w1 = ex * w0;
        g_w2[2 * t] = w0;
        g_w2[2 * t + 1] = w1;
        int s0 = atomicAdd(&g_cnt[i0], 1);
        g_tokp[i0 * TOK + s0] = t;                          // k = 0
        int s1 = atomicAdd(&g_cnt[i1], 1);
        g_tokp[i1 * TOK + s1] = t | 0x80000000;             // k = 1
    }
}

// ---------------- GEMM1: h = silu(x@Wg)*(x@Wu); block 128x64, 4 warps 64x32 -----
struct SmemG1 {
    float A[3][BM][A_ST];     // 55296 B
    float Bg[3][BK][B1_ST];   // 27648 B
    float Bu[3][BK][B1_ST];   // 27648 B
    int   tok[BM];
};                            // ~111 KB -> 2 CTAs/SM

__device__ __forceinline__ void g1_load(SmemG1* s, int st, int k0,
                                        const int* tok_s, int e, int n_base, int tid) {
#pragma unroll
    for (int i = 0; i < 8; i++) {                  // A: 128x32 = 1024 float4
        int idx = tid + i * 128;
        int row = idx >> 3, c = idx & 7;
        cp16(saddr(&s->A[st][row][c * 4]), &g_xr[(size_t)tok_s[row] * HD + k0 + c * 4]);
    }
    const float* bg = g_wg + ((size_t)e * HD + k0) * ID + n_base;
    const float* bu = g_wu + ((size_t)e * HD + k0) * ID + n_base;
#pragma unroll
    for (int i = 0; i < 4; i++) {                  // Bg/Bu: 32x64 = 512 float4 each
        int idx = tid + i * 128;
        int kr = idx >> 4, c = idx & 15;
        cp16(saddr(&s->Bg[st][kr][c * 4]), bg + (size_t)kr * ID + c * 4);
        cp16(saddr(&s->Bu[st][kr][c * 4]), bu + (size_t)kr * ID + c * 4);
    }
}

#define KT1 (HD / BK)   // 64

__global__ void __launch_bounds__(128, 2) gemm1_kernel() {
    extern __shared__ __align__(16) char smem_raw[];
    SmemG1* s = (SmemG1*)smem_raw;

    int e = blockIdx.z;
    int cnt = g_cnt[e];
    int m_base = blockIdx.y * BM;
    if (m_base >= cnt) return;
    int n_base = blockIdx.x * BN1;
    int tid = threadIdx.x;

    {
        int m = m_base + tid;
        s->tok[tid] = (m < cnt) ? (g_tokp[e * TOK + m] & 0x7fffffff) : 0;
    }
    __syncthreads();

    int wid = tid >> 5, lane = tid & 31;
    int wm = wid >> 1, wn = wid & 1;               // 2 x 2 warps, warp 64x32
    int r = lane >> 2, cq = lane & 3;

    float acc_g[4][4][4], acc_u[4][4][4];
#pragma unroll
    for (int mf = 0; mf < 4; mf++)
#pragma unroll
        for (int nf = 0; nf < 4; nf++)
#pragma unroll
            for (int k = 0; k < 4; k++) { acc_g[mf][nf][k] = 0.f; acc_u[mf][nf][k] = 0.f; }

    g1_load(s, 0, 0, s->tok, e, n_base, tid);  cp_commit();
    g1_load(s, 1, BK, s->tok, e, n_base, tid); cp_commit();

    for (int kt = 0; kt < KT1; kt++) {
        cp_wait<1>();
        __syncthreads();
        int nxt = kt + 2;
        if (nxt < KT1) g1_load(s, nxt % 3, nxt * BK, s->tok, e, n_base, tid);
        cp_commit();

        int sg = kt % 3;
#pragma unroll
        for (int kk = 0; kk < BK / 8; kk++) {
            int k8 = kk * 8;
            uint32_t a[4][4];
#pragma unroll
            for (int mf = 0; mf < 4; mf++) {
                int row = wm * 64 + mf * 16;
                a[mf][0] = __float_as_uint(s->A[sg][row + r][k8 + cq]);
                a[mf][1] = __float_as_uint(s->A[sg][row + r + 8][k8 + cq]);
                a[mf][2] = __float_as_uint(s->A[sg][row + r][k8 + cq + 4]);
                a[mf][3] = __float_as_uint(s->A[sg][row + r + 8][k8 + cq + 4]);
            }
            uint32_t bg[4][2], bu[4][2];
#pragma unroll
            for (int nf = 0; nf < 4; nf++) {
                int coln = wn * 32 + nf * 8 + r;
                bg[nf][0] = __float_as_uint(s->Bg[sg][k8 + cq][coln]);
                bg[nf][1] = __float_as_uint(s->Bg[sg][k8 + cq + 4][coln]);
                bu[nf][0] = __float_as_uint(s->Bu[sg][k8 + cq][coln]);
                bu[nf][1] = __float_as_uint(s->Bu[sg][k8 + cq + 4][coln]);
            }
#pragma unroll
            for (int mf = 0; mf < 4; mf++)
#pragma unroll
                for (int nf = 0; nf < 4; nf++) {
                    mma_tf32(acc_g[mf][nf], a[mf], bg[nf]);
                    mma_tf32(acc_u[mf][nf], a[mf], bu[nf]);
                }
        }
    }

    // epilogue: silu(g)*u -> tf32 round -> g_h
#pragma unroll
    for (int mf = 0; mf < 4; mf++) {
#pragma unroll
        for (int nf = 0; nf < 4; nf++) {
            int rl = wm * 64 + mf * 16 + r;
            int col = n_base + wn * 32 + nf * 8 + cq * 2;
            if (m_base + rl < cnt) {
                float g0 = acc_g[mf][nf][0], u0 = acc_u[mf][nf][0];
                float g1 = acc_g[mf][nf][1], u1 = acc_u[mf][nf][1];
                float v0 = (g0 / (1.f + __expf(-g0))) * u0;
                float v1 = (g1 / (1.f + __expf(-g1))) * u1;
                float2* p = (float2*)&g_h[((size_t)e * TOK + m_base + rl) * ID + col];
                *p = make_float2(tf32_round(v0), tf32_round(v1));
            }
            if (m_base + rl + 8 < cnt) {
                float g0 = acc_g[mf][nf][2], u0 = acc_u[mf][nf][2];
                float g1 = acc_g[mf][nf][3], u1 = acc_u[mf][nf][3];
                float v0 = (g0 / (1.f + __expf(-g0))) * u0;
                float v1 = (g1 / (1.f + __expf(-g1))) * u1;
                float2* p = (float2*)&g_h[((size_t)e * TOK + m_base + rl + 8) * ID + col];
                *p = make_float2(tf32_round(v0), tf32_round(v1));
            }
        }
    }
}

// ---------------- GEMM2: y[k][t] = h @ Wd; block 128x128, 8 warps 64x32 ---------
struct SmemG2 {
    float A[3][BM][A_ST];      // 55296 B
    float B[3][BK][B2_ST];     // 52224 B
    int   tokp[BM];
};                             // ~108 KB -> 2 CTAs/SM

__device__ __forceinline__ void g2_load(SmemG2* s, int st, int k0,
                                        int e, int m_base, int n_base, int tid) {
    const float* arow = g_h + ((size_t)e * TOK + m_base) * ID + k0;
    const float* brow = g_wd + ((size_t)e * ID + k0) * HD + n_base;
#pragma unroll
    for (int i = 0; i < 4; i++) {                  // A: 1024 float4
        int idx = tid + i * 256;
        int row = idx >> 3, c = idx & 7;
        cp16(saddr(&s->A[st][row][c * 4]), arow + (size_t)row * ID + c * 4);
    }
#pragma unroll
    for (int i = 0; i < 4; i++) {                  // B: 32x128 = 1024 float4
        int idx = tid + i * 256;
        int kr = idx >> 5, c = idx & 31;
        cp16(saddr(&s->B[st][kr][c * 4]), brow + (size_t)kr * HD + c * 4);
    }
}

#define KT2 (ID / BK)   // 44

__global__ void __launch_bounds__(256, 2) gemm2_kernel() {
    extern __shared__ __align__(16) char smem_raw[];
    SmemG2* s = (SmemG2*)smem_raw;

    int e = blockIdx.z;
    int cnt = g_cnt[e];
    int m_base = blockIdx.y * BM;
    if (m_base >= cnt) return;
    int n_base = blockIdx.x * BN2;
    int tid = threadIdx.x;

    if (tid < BM) {
        int m = m_base + tid;
        s->tokp[tid] = (m < cnt) ? g_tokp[e * TOK + m] : 0;
    }
    __syncthreads();

    int wid = tid >> 5, lane = tid & 31;
    int wm = wid >> 2, wn = wid & 3;               // 2 x 4 warps, warp 64x32
    int r = lane >> 2, cq = lane & 3;

    float acc[4][4][4];
#pragma unroll
    for (int mf = 0; mf < 4; mf++)
#pragma unroll
        for (int nf = 0; nf < 4; nf++)
#pragma unroll
            for (int k = 0; k < 4; k++) acc[mf][nf][k] = 0.f;

    g2_load(s, 0, 0, e, m_base, n_base, tid);  cp_commit();
    g2_load(s, 1, BK, e, m_base, n_base, tid); cp_commit();

    for (int kt = 0; kt < KT2; kt++) {
        cp_wait<1>();
        __syncthreads();
        int nxt = kt + 2;
        if (nxt < KT2) g2_load(s, nxt % 3, nxt * BK, e, m_base, n_base, tid);
        cp_commit();

        int sg = kt % 3;
#pragma unroll
        for (int kk = 0; kk < BK / 8; kk++) {
            int k8 = kk * 8;
            uint32_t a[4][4];
#pragma unroll
            for (int mf = 0; mf < 4; mf++) {
                int row = wm * 64 + mf * 16;
                a[mf][0] = __float_as_uint(s->A[sg][row + r][k8 + cq]);
                a[mf][1] = __float_as_uint(s->A[sg][row + r + 8][k8 + cq]);
                a[mf][2] = __float_as_uint(s->A[sg][row + r][k8 + cq + 4]);
                a[mf][3] = __float_as_uint(s->A[sg][row + r + 8][k8 + cq + 4]);
            }
            uint32_t b[4][2];
#pragma unroll
            for (int nf = 0; nf < 4; nf++) {
                int coln = wn * 32 + nf * 8 + r;
                b[nf][0] = __float_as_uint(s->B[sg][k8 + cq][coln]);
                b[nf][1] = __float_as_uint(s->B[sg][k8 + cq + 4][coln]);
            }
#pragma unroll
            for (int mf = 0; mf < 4; mf++)
#pragma unroll
                for (int nf = 0; nf < 4; nf++)
                    mma_tf32(acc[mf][nf], a[mf], b[nf]);
        }
    }

    // epilogue: plain stores to g_y[k][t] (no weights, no atomics)
#pragma unroll
    for (int mf = 0; mf < 4; mf++) {
#pragma unroll
        for (int nf = 0; nf < 4; nf++) {
            int rl = wm * 64 + mf * 16 + r;
            int col = n_base + wn * 32 + nf * 8 + cq * 2;
            if (m_base + rl < cnt) {
                int pk = s->tokp[rl];
                int t = pk & 0x7fffffff;
                int k = (uint32_t)pk >> 31;
                float2* p = (float2*)&g_y[((size_t)k * TOK + t) * HD + col];
                *p = make_float2(acc[mf][nf][0], acc[mf][nf][1]);
            }
            if (m_base + rl + 8 < cnt) {
                int pk = s->tokp[rl + 8];
                int t = pk & 0x7fffffff;
                int k = (uint32_t)pk >> 31;
                float2* p = (float2*)&g_y[((size_t)k * TOK + t) * HD + col];
                *p = make_float2(acc[mf][nf][2], acc[mf][nf][3]);
            }
        }
    }
}

// ---------------- combine: out = w0*y0 + w1*y1 ----------------------------------
__global__ void combine_kernel(float4* __restrict__ out) {
    const int n4 = TOK * HD / 4;
    const float4* y0 = (const float4*)g_y;
    const float4* y1 = y0 + n4;
    for (int i = blockIdx.x * blockDim.x + threadIdx.x; i < n4; i += gridDim.x * blockDim.x) {
        int t = i / (HD / 4);
        float w0 = g_w2[2 * t], w1 = g_w2[2 * t + 1];
        float4 a = y0[i], b = y1[i];
        float4 o;
        o.x = w0 * a.x + w1 * b.x;
        o.y = w0 * a.y + w1 * b.y;
        o.z = w0 * a.z + w1 * b.z;
        o.w = w0 * a.w + w1 * b.w;
        out[i] = o;
    }
}

// ---------------- host launcher -------------------------------------------------
extern "C" void kernel_launch(void* const* d_in, const int* in_sizes, int n_in,
                              void* d_out, int out_size) {
    const float* x  = (const float*)d_in[0];
    const float* gw = (const float*)d_in[1];
    const float* wg = (const float*)d_in[2];
    const float* wu = (const float*)d_in[3];
    const float* wd = (const float*)d_in[4];
    (void)in_sizes; (void)n_in; (void)out_size;

    zero_cnt_kernel<<<1, 32>>>();

    round_tf32_kernel<<<2048, 256>>>((const float4*)wg, 1, NE * HD * ID / 4);
    round_tf32_kernel<<<2048, 256>>>((const float4*)wu, 2, NE * HD * ID / 4);
    round_tf32_kernel<<<2048, 256>>>((const float4*)wd, 3, NE * ID * HD / 4);

    cudaFuncSetAttribute(router_kernel, cudaFuncAttributeMaxDynamicSharedMemorySize,
                         NE * HD * (int)sizeof(float));
    router_kernel<<<TOK * 32 / 256, 256, NE * HD * sizeof(float)>>>(x, gw);

    cudaFuncSetAttribute(gemm1_kernel, cudaFuncAttributeMaxDynamicSharedMemorySize,
                         (int)sizeof(SmemG1));
    dim3 grid1(ID / BN1, TOK / BM, NE);     // 22 x 64 x 8
    gemm1_kernel<<<grid1, 128, sizeof(SmemG1)>>>();

    cudaFuncSetAttribute(gemm2_kernel, cudaFuncAttributeMaxDynamicSharedMemorySize,
                         (int)sizeof(SmemG2));
    dim3 grid2(HD / BN2, TOK / BM, NE);     // 16 x 64 x 8
    gemm2_kernel<<<grid2, 256, sizeof(SmemG2)>>>();

    combine_kernel<<<2048, 256>>>((float4*)d_out);
}

// round 5
// speedup vs baseline: 1.3086x; 1.0638x over previous
#include <cuda_runtime.h>
#include <cuda_fp16.h>
#include <cstdint>

#define TOK 8192
#define HD  2048
#define ID  1408
#define NE  8

#define BM  128
#define BN  128
#define BK  32
#define A_ST 40      // 32 + 8 pad (halves) -> 80B row stride
#define B_ST 136     // 128 + 8 pad (halves) -> 272B row stride

// ---------------- device scratch (no allocations allowed) ----------------------
__device__ __half g_xh[(size_t)TOK * HD];       // fp16 x
__device__ __half g_wgh[(size_t)NE * HD * ID];  // fp16 weights, native [k][n]
__device__ __half g_wuh[(size_t)NE * HD * ID];
__device__ __half g_wdh[(size_t)NE * ID * HD];
__device__ int    g_cnt[NE];
__device__ int    g_tokp[NE * TOK];             // token | (k<<31)
__device__ float  g_w2[TOK * 2];                // per-token (w0, w1)
__device__ __half g_hh[(size_t)NE * TOK * ID];  // fp16 intermediate (slot-indexed)
__device__ float  g_y[(size_t)2 * TOK * HD];    // unweighted expert outputs per k

// ---------------- helpers ------------------------------------------------------
__device__ __forceinline__ uint32_t saddr(const void* p) {
    return (uint32_t)__cvta_generic_to_shared(p);
}
__device__ __forceinline__ void cp16(uint32_t dst, const void* src) {
    asm volatile("cp.async.cg.shared.global [%0], [%1], 16;" :: "r"(dst), "l"(src));
}
__device__ __forceinline__ void cp_commit() { asm volatile("cp.async.commit_group;"); }
template <int N>
__device__ __forceinline__ void cp_wait() { asm volatile("cp.async.wait_group %0;" :: "n"(N)); }

__device__ __forceinline__ void ldsm_x4(uint32_t* r, uint32_t addr) {
    asm volatile("ldmatrix.sync.aligned.m8n8.x4.shared.b16 {%0,%1,%2,%3}, [%4];"
                 : "=r"(r[0]), "=r"(r[1]), "=r"(r[2]), "=r"(r[3]) : "r"(addr));
}
__device__ __forceinline__ void ldsm_x4t(uint32_t* r, uint32_t addr) {
    asm volatile("ldmatrix.sync.aligned.m8n8.x4.trans.shared.b16 {%0,%1,%2,%3}, [%4];"
                 : "=r"(r[0]), "=r"(r[1]), "=r"(r[2]), "=r"(r[3]) : "r"(addr));
}
__device__ __forceinline__ void mma_f16(float d[4], const uint32_t a[4], const uint32_t b[2]) {
    asm volatile(
        "mma.sync.aligned.m16n8k16.row.col.f32.f16.f16.f32 "
        "{%0,%1,%2,%3}, {%4,%5,%6,%7}, {%8,%9}, {%0,%1,%2,%3};"
        : "+f"(d[0]), "+f"(d[1]), "+f"(d[2]), "+f"(d[3])
        : "r"(a[0]), "r"(a[1]), "r"(a[2]), "r"(a[3]), "r"(b[0]), "r"(b[1]));
}

// ---------------- small kernels ------------------------------------------------
__global__ void zero_cnt_kernel() {
    if (threadIdx.x < NE) g_cnt[threadIdx.x] = 0;
}

// fp32 -> fp16, which: 1->g_wgh, 2->g_wuh, 3->g_wdh
__global__ void conv_half_kernel(const float4* __restrict__ in, int which, int n4) {
    __half* outh = which == 1 ? g_wgh : which == 2 ? g_wuh : g_wdh;
    uint2* out = (uint2*)outh;
    for (int i = blockIdx.x * blockDim.x + threadIdx.x; i < n4; i += gridDim.x * blockDim.x) {
        float4 v = in[i];
        __half2 lo = __floats2half2_rn(v.x, v.y);
        __half2 hi = __floats2half2_rn(v.z, v.w);
        uint2 o;
        o.x = *(uint32_t*)&lo;
        o.y = *(uint32_t*)&hi;
        out[i] = o;
    }
}

// Router + fused fp16 conversion of x. One warp per token.
__global__ void router_kernel(const float* __restrict__ x, const float* __restrict__ gw) {
    extern __shared__ float s_gw[];  // NE*HD = 64 KB
    for (int i = threadIdx.x; i < NE * HD; i += blockDim.x) s_gw[i] = gw[i];
    __syncthreads();

    int gtid = blockIdx.x * blockDim.x + threadIdx.x;
    int t = gtid >> 5, lane = gtid & 31;
    if (t >= TOK) return;

    float acc[NE];
#pragma unroll
    for (int e = 0; e < NE; e++) acc[e] = 0.f;

    const float* xr = x + (size_t)t * HD;
    __half* xo = g_xh + (size_t)t * HD;
    for (int i = lane; i < HD; i += 32) {
        float xv = xr[i];
        xo[i] = __float2half_rn(xv);
#pragma unroll
        for (int e = 0; e < NE; e++) acc[e] += xv * s_gw[e * HD + i];
    }
#pragma unroll
    for (int e = 0; e < NE; e++) {
#pragma unroll
        for (int off = 16; off > 0; off >>= 1)
            acc[e] += __shfl_xor_sync(0xffffffffu, acc[e], off);
    }
    if (lane == 0) {
        int i0 = 0; float l0 = acc[0];
#pragma unroll
        for (int e = 1; e < NE; e++) if (acc[e] > l0) { l0 = acc[e]; i0 = e; }
        int i1 = -1; float l1 = -1e30f;
#pragma unroll
        for (int e = 0; e < NE; e++) if (e != i0 && acc[e] > l1) { l1 = acc[e]; i1 = e; }
        float ex = __expf(l1 - l0);
        float w0 = 1.f / (1.f + ex);
        float w1 = ex * w0;
        g_w2[2 * t] = w0;
        g_w2[2 * t + 1] = w1;
        int s0 = atomicAdd(&g_cnt[i0], 1);
        g_tokp[i0 * TOK + s0] = t;                          // k = 0
        int s1 = atomicAdd(&g_cnt[i1], 1);
        g_tokp[i1 * TOK + s1] = t | 0x80000000;             // k = 1
    }
}

// ---------------- GEMM1: h = silu(x@Wg)*(x@Wu); 128x128, 8 warps 64x32, fp16 ----
struct SmemG1 {
    __half A[3][BM][A_ST];    // 30720 B
    __half Bg[3][BK][B_ST];   // 26112 B
    __half Bu[3][BK][B_ST];   // 26112 B
    int    tok[BM];
};                            // ~81.5 KB -> 2 CTAs/SM

__device__ __forceinline__ void g1_load(SmemG1* s, int st, int k0,
                                        const int* tok_s, int e, int n_base, int tid) {
#pragma unroll
    for (int i = 0; i < 2; i++) {                 // A: 128 rows x 2 chunks(16B)
        int idx = tid + i * 256;
        int row = idx >> 2, c = idx & 3;
        cp16(saddr(&s->A[st][row][c * 8]), &g_xh[(size_t)tok_s[row] * HD + k0 + c * 8]);
    }
    const __half* bg = g_wgh + ((size_t)e * HD + k0) * ID + n_base;
    const __half* bu = g_wuh + ((size_t)e * HD + k0) * ID + n_base;
#pragma unroll
    for (int i = 0; i < 2; i++) {                 // Bg/Bu: 32 rows x 16 chunks
        int idx = tid + i * 256;
        int kr = idx >> 4, c = idx & 15;
        cp16(saddr(&s->Bg[st][kr][c * 8]), bg + (size_t)kr * ID + c * 8);
        cp16(saddr(&s->Bu[st][kr][c * 8]), bu + (size_t)kr * ID + c * 8);
    }
}

#define KT1 (HD / BK)   // 64

__global__ void __launch_bounds__(256, 2) gemm1_kernel() {
    extern __shared__ __align__(16) char smem_raw[];
    SmemG1* s = (SmemG1*)smem_raw;

    int e = blockIdx.z;
    int cnt = g_cnt[e];
    int m_base = blockIdx.y * BM;
    if (m_base >= cnt) return;
    int n_base = blockIdx.x * BN;
    int tid = threadIdx.x;

    if (tid < BM) {
        int m = m_base + tid;
        s->tok[tid] = (m < cnt) ? (g_tokp[e * TOK + m] & 0x7fffffff) : 0;
    }
    __syncthreads();

    int wid = tid >> 5, lane = tid & 31;
    int wm = wid >> 2, wn = wid & 3;               // 2 x 4 warps, warp 64x32
    int r = lane >> 2, cq = lane & 3;
    int lrow = lane & 15, lcol = (lane >> 4) << 3;

    float acc_g[4][4][4], acc_u[4][4][4];
#pragma unroll
    for (int mf = 0; mf < 4; mf++)
#pragma unroll
        for (int nf = 0; nf < 4; nf++)
#pragma unroll
            for (int k = 0; k < 4; k++) { acc_g[mf][nf][k] = 0.f; acc_u[mf][nf][k] = 0.f; }

    g1_load(s, 0, 0, s->tok, e, n_base, tid);  cp_commit();
    g1_load(s, 1, BK, s->tok, e, n_base, tid); cp_commit();

    for (int kt = 0; kt < KT1; kt++) {
        cp_wait<1>();
        __syncthreads();
        int nxt = kt + 2;
        if (nxt < KT1) g1_load(s, nxt % 3, nxt * BK, s->tok, e, n_base, tid);
        cp_commit();

        int sg = kt % 3;
        uint32_t sA  = saddr(&s->A[sg][0][0]);
        uint32_t sBg = saddr(&s->Bg[sg][0][0]);
        uint32_t sBu = saddr(&s->Bu[sg][0][0]);
#pragma unroll
        for (int ks = 0; ks < 2; ks++) {
            int k16 = ks * 16;
            uint32_t a[4][4];
#pragma unroll
            for (int mf = 0; mf < 4; mf++)
                ldsm_x4(a[mf], sA + 2 * ((wm * 64 + mf * 16 + lrow) * A_ST + k16 + lcol));
            uint32_t bg[2][4], bu[2][4];
#pragma unroll
            for (int ng = 0; ng < 2; ng++) {
                uint32_t off = 2 * ((k16 + lrow) * B_ST + wn * 32 + ng * 16 + lcol);
                ldsm_x4t(bg[ng], sBg + off);
                ldsm_x4t(bu[ng], sBu + off);
            }
#pragma unroll
            for (int mf = 0; mf < 4; mf++)
#pragma unroll
                for (int nf = 0; nf < 4; nf++) {
                    mma_f16(acc_g[mf][nf], a[mf], &bg[nf >> 1][(nf & 1) * 2]);
                    mma_f16(acc_u[mf][nf], a[mf], &bu[nf >> 1][(nf & 1) * 2]);
                }
        }
    }

    // epilogue: silu(g)*u -> fp16 -> g_hh
#pragma unroll
    for (int mf = 0; mf < 4; mf++) {
#pragma unroll
        for (int nf = 0; nf < 4; nf++) {
            int rl = wm * 64 + mf * 16 + r;
            int col = n_base + wn * 32 + nf * 8 + cq * 2;
            if (m_base + rl < cnt) {
                float g0 = acc_g[mf][nf][0], u0 = acc_u[mf][nf][0];
                float g1 = acc_g[mf][nf][1], u1 = acc_u[mf][nf][1];
                float v0 = (g0 / (1.f + __expf(-g0))) * u0;
                float v1 = (g1 / (1.f + __expf(-g1))) * u1;
                __half2* p = (__half2*)&g_hh[((size_t)e * TOK + m_base + rl) * ID + col];
                *p = __floats2half2_rn(v0, v1);
            }
            if (m_base + rl + 8 < cnt) {
                float g0 = acc_g[mf][nf][2], u0 = acc_u[mf][nf][2];
                float g1 = acc_g[mf][nf][3], u1 = acc_u[mf][nf][3];
                float v0 = (g0 / (1.f + __expf(-g0))) * u0;
                float v1 = (g1 / (1.f + __expf(-g1))) * u1;
                __half2* p = (__half2*)&g_hh[((size_t)e * TOK + m_base + rl + 8) * ID + col];
                *p = __floats2half2_rn(v0, v1);
            }
        }
    }
}

// ---------------- GEMM2: y[k][t] = h @ Wd; 128x128, 8 warps 64x32, fp16, 4stg ---
struct SmemG2 {
    __half A[4][BM][A_ST];     // 40960 B
    __half B[4][BK][B_ST];     // 34816 B
    int    tokp[BM];
};                             // ~74.5 KB -> 2 CTAs/SM

__device__ __forceinline__ void g2_load(SmemG2* s, int st, int k0,
                                        int e, int m_base, int n_base, int tid) {
    const __half* arow = g_hh + ((size_t)e * TOK + m_base) * ID + k0;
    const __half* brow = g_wdh + ((size_t)e * ID + k0) * HD + n_base;
#pragma unroll
    for (int i = 0; i < 2; i++) {
        int idx = tid + i * 256;
        int row = idx >> 2, c = idx & 3;
        cp16(saddr(&s->A[st][row][c * 8]), arow + (size_t)row * ID + c * 8);
    }
#pragma unroll
    for (int i = 0; i < 2; i++) {
        int idx = tid + i * 256;
        int kr = idx >> 4, c = idx & 15;
        cp16(saddr(&s->B[st][kr][c * 8]), brow + (size_t)kr * HD + c * 8);
    }
}

#define KT2 (ID / BK)   // 44

__global__ void __launch_bounds__(256, 2) gemm2_kernel() {
    extern __shared__ __align__(16) char smem_raw[];
    SmemG2* s = (SmemG2*)smem_raw;

    int e = blockIdx.z;
    int cnt = g_cnt[e];
    int m_base = blockIdx.y * BM;
    if (m_base >= cnt) return;
    int n_base = blockIdx.x * BN;
    int tid = threadIdx.x;

    if (tid < BM) {
        int m = m_base + tid;
        s->tokp[tid] = (m < cnt) ? g_tokp[e * TOK + m] : 0;
    }
    __syncthreads();

    int wid = tid >> 5, lane = tid & 31;
    int wm = wid >> 2, wn = wid & 3;
    int r = lane >> 2, cq = lane & 3;
    int lrow = lane & 15, lcol = (lane >> 4) << 3;

    float acc[4][4][4];
#pragma unroll
    for (int mf = 0; mf < 4; mf++)
#pragma unroll
        for (int nf = 0; nf < 4; nf++)
#pragma unroll
            for (int k = 0; k < 4; k++) acc[mf][nf][k] = 0.f;

    g2_load(s, 0, 0, e, m_base, n_base, tid);      cp_commit();
    g2_load(s, 1, BK, e, m_base, n_base, tid);     cp_commit();
    g2_load(s, 2, 2 * BK, e, m_base, n_base, tid); cp_commit();

    for (int kt = 0; kt < KT2; kt++) {
        cp_wait<2>();
        __syncthreads();
        int nxt = kt + 3;
        if (nxt < KT2) g2_load(s, nxt & 3, nxt * BK, e, m_base, n_base, tid);
        cp_commit();

        int sg = kt & 3;
        uint32_t sA = saddr(&s->A[sg][0][0]);
        uint32_t sB = saddr(&s->B[sg][0][0]);
#pragma unroll
        for (int ks = 0; ks < 2; ks++) {
            int k16 = ks * 16;
            uint32_t a[4][4];
#pragma unroll
            for (int mf = 0; mf < 4; mf++)
                ldsm_x4(a[mf], sA + 2 * ((wm * 64 + mf * 16 + lrow) * A_ST + k16 + lcol));
            uint32_t b[2][4];
#pragma unroll
            for (int ng = 0; ng < 2; ng++) {
                uint32_t off = 2 * ((k16 + lrow) * B_ST + wn * 32 + ng * 16 + lcol);
                ldsm_x4t(b[ng], sB + off);
            }
#pragma unroll
            for (int mf = 0; mf < 4; mf++)
#pragma unroll
                for (int nf = 0; nf < 4; nf++)
                    mma_f16(acc[mf][nf], a[mf], &b[nf >> 1][(nf & 1) * 2]);
        }
    }

    // epilogue: plain stores to g_y[k][t]
#pragma unroll
    for (int mf = 0; mf < 4; mf++) {
#pragma unroll
        for (int nf = 0; nf < 4; nf++) {
            int rl = wm * 64 + mf * 16 + r;
            int col = n_base + wn * 32 + nf * 8 + cq * 2;
            if (m_base + rl < cnt) {
                int pk = s->tokp[rl];
                int t = pk & 0x7fffffff;
                int k = (uint32_t)pk >> 31;
                float2* p = (float2*)&g_y[((size_t)k * TOK + t) * HD + col];
                *p = make_float2(acc[mf][nf][0], acc[mf][nf][1]);
            }
            if (m_base + rl + 8 < cnt) {
                int pk = s->tokp[rl + 8];
                int t = pk & 0x7fffffff;
                int k = (uint32_t)pk >> 31;
                float2* p = (float2*)&g_y[((size_t)k * TOK + t) * HD + col];
                *p = make_float2(acc[mf][nf][2], acc[mf][nf][3]);
            }
        }
    }
}

// ---------------- combine: out = w0*y0 + w1*y1 ----------------------------------
__global__ void combine_kernel(float4* __restrict__ out) {
    const int n4 = TOK * HD / 4;
    const float4* y0 = (const float4*)g_y;
    const float4* y1 = y0 + n4;
    for (int i = blockIdx.x * blockDim.x + threadIdx.x; i < n4; i += gridDim.x * blockDim.x) {
        int t = i / (HD / 4);
        float w0 = g_w2[2 * t], w1 = g_w2[2 * t + 1];
        float4 a = y0[i], b = y1[i];
        float4 o;
        o.x = w0 * a.x + w1 * b.x;
        o.y = w0 * a.y + w1 * b.y;
        o.z = w0 * a.z + w1 * b.z;
        o.w = w0 * a.w + w1 * b.w;
        out[i] = o;
    }
}

// ---------------- host launcher -------------------------------------------------
extern "C" void kernel_launch(void* const* d_in, const int* in_sizes, int n_in,
                              void* d_out, int out_size) {
    const float* x  = (const float*)d_in[0];
    const float* gw = (const float*)d_in[1];
    const float* wg = (const float*)d_in[2];
    const float* wu = (const float*)d_in[3];
    const float* wd = (const float*)d_in[4];
    (void)in_sizes; (void)n_in; (void)out_size;

    zero_cnt_kernel<<<1, 32>>>();

    conv_half_kernel<<<2048, 256>>>((const float4*)wg, 1, NE * HD * ID / 4);
    conv_half_kernel<<<2048, 256>>>((const float4*)wu, 2, NE * HD * ID / 4);
    conv_half_kernel<<<2048, 256>>>((const float4*)wd, 3, NE * ID * HD / 4);

    cudaFuncSetAttribute(router_kernel, cudaFuncAttributeMaxDynamicSharedMemorySize,
                         NE * HD * (int)sizeof(float));
    router_kernel<<<TOK * 32 / 256, 256, NE * HD * sizeof(float)>>>(x, gw);

    cudaFuncSetAttribute(gemm1_kernel, cudaFuncAttributeMaxDynamicSharedMemorySize,
                         (int)sizeof(SmemG1));
    dim3 grid1(ID / BN, TOK / BM, NE);     // 11 x 64 x 8
    gemm1_kernel<<<grid1, 256, sizeof(SmemG1)>>>();

    cudaFuncSetAttribute(gemm2_kernel, cudaFuncAttributeMaxDynamicSharedMemorySize,
                         (int)sizeof(SmemG2));
    dim3 grid2(HD / BN, TOK / BM, NE);     // 16 x 64 x 8
    gemm2_kernel<<<grid2, 256, sizeof(SmemG2)>>>();

    combine_kernel<<<2048, 256>>>((float4*)d_out);
}

// round 6
// speedup vs baseline: 2.0752x; 1.5858x over previous
#include <cuda_runtime.h>
#include <cuda_fp16.h>
#include <cstdint>

#define TOK 8192
#define HD  2048
#define ID  1408
#define NE  8

#define BM   128
#define BK   64
#define BN1  128
#define BN2  256
#define A_ST 72      // 64 + 8 halves -> 144B row stride
#define B1_ST 136    // 128 + 8 halves -> 272B
#define B2_ST 264    // 256 + 8 halves -> 528B

// ---------------- device scratch (no allocations allowed) ----------------------
__device__ __half g_xh[(size_t)TOK * HD];       // fp16 x
__device__ __half g_wgh[(size_t)NE * HD * ID];  // fp16 weights, native [k][n]
__device__ __half g_wuh[(size_t)NE * HD * ID];
__device__ __half g_wdh[(size_t)NE * ID * HD];
__device__ int    g_cnt[NE];
__device__ int    g_tokp[NE * TOK];             // token | (k<<31)
__device__ float  g_w2[TOK * 2];                // per-token (w0, w1)
__device__ __half g_hh[(size_t)NE * TOK * ID];  // fp16 intermediate (slot-indexed)
__device__ float  g_y[(size_t)2 * TOK * HD];    // unweighted expert outputs per k

// ---------------- helpers ------------------------------------------------------
__device__ __forceinline__ uint32_t saddr(const void* p) {
    return (uint32_t)__cvta_generic_to_shared(p);
}
__device__ __forceinline__ void cp16(uint32_t dst, const void* src) {
    asm volatile("cp.async.cg.shared.global [%0], [%1], 16;" :: "r"(dst), "l"(src));
}
__device__ __forceinline__ void cp_commit() { asm volatile("cp.async.commit_group;"); }
template <int N>
__device__ __forceinline__ void cp_wait() { asm volatile("cp.async.wait_group %0;" :: "n"(N)); }

__device__ __forceinline__ void ldsm_x4(uint32_t* r, uint32_t addr) {
    asm volatile("ldmatrix.sync.aligned.m8n8.x4.shared.b16 {%0,%1,%2,%3}, [%4];"
                 : "=r"(r[0]), "=r"(r[1]), "=r"(r[2]), "=r"(r[3]) : "r"(addr));
}
__device__ __forceinline__ void ldsm_x4t(uint32_t* r, uint32_t addr) {
    asm volatile("ldmatrix.sync.aligned.m8n8.x4.trans.shared.b16 {%0,%1,%2,%3}, [%4];"
                 : "=r"(r[0]), "=r"(r[1]), "=r"(r[2]), "=r"(r[3]) : "r"(addr));
}
__device__ __forceinline__ void mma_f16(float d[4], const uint32_t a[4], const uint32_t b[2]) {
    asm volatile(
        "mma.sync.aligned.m16n8k16.row.col.f32.f16.f16.f32 "
        "{%0,%1,%2,%3}, {%4,%5,%6,%7}, {%8,%9}, {%0,%1,%2,%3};"
        : "+f"(d[0]), "+f"(d[1]), "+f"(d[2]), "+f"(d[3])
        : "r"(a[0]), "r"(a[1]), "r"(a[2]), "r"(a[3]), "r"(b[0]), "r"(b[1]));
}

// ---------------- small kernels ------------------------------------------------
__global__ void zero_cnt_kernel() {
    if (threadIdx.x < NE) g_cnt[threadIdx.x] = 0;
}

// single conv pass for all 3 weight tensors (blockIdx.z selects)
__global__ void conv_half_kernel(const float4* __restrict__ wg,
                                 const float4* __restrict__ wu,
                                 const float4* __restrict__ wd) {
    const int n4 = NE * HD * ID / 4;
    const float4* in = blockIdx.z == 0 ? wg : blockIdx.z == 1 ? wu : wd;
    uint2* out = (uint2*)(blockIdx.z == 0 ? g_wgh : blockIdx.z == 1 ? g_wuh : g_wdh);
    for (int i = blockIdx.x * blockDim.x + threadIdx.x; i < n4; i += gridDim.x * blockDim.x) {
        float4 v = in[i];
        __half2 lo = __floats2half2_rn(v.x, v.y);
        __half2 hi = __floats2half2_rn(v.z, v.w);
        uint2 o;
        o.x = *(uint32_t*)&lo;
        o.y = *(uint32_t*)&hi;
        out[i] = o;
    }
}

// Router + fused fp16 conversion of x. One warp per token.
__global__ void router_kernel(const float* __restrict__ x, const float* __restrict__ gw) {
    extern __shared__ float s_gw[];  // NE*HD = 64 KB
    for (int i = threadIdx.x; i < NE * HD; i += blockDim.x) s_gw[i] = gw[i];
    __syncthreads();

    int gtid = blockIdx.x * blockDim.x + threadIdx.x;
    int t = gtid >> 5, lane = gtid & 31;
    if (t >= TOK) return;

    float acc[NE];
#pragma unroll
    for (int e = 0; e < NE; e++) acc[e] = 0.f;

    const float* xr = x + (size_t)t * HD;
    __half* xo = g_xh + (size_t)t * HD;
    for (int i = lane; i < HD; i += 32) {
        float xv = xr[i];
        xo[i] = __float2half_rn(xv);
#pragma unroll
        for (int e = 0; e < NE; e++) acc[e] += xv * s_gw[e * HD + i];
    }
#pragma unroll
    for (int e = 0; e < NE; e++) {
#pragma unroll
        for (int off = 16; off > 0; off >>= 1)
            acc[e] += __shfl_xor_sync(0xffffffffu, acc[e], off);
    }
    if (lane == 0) {
        int i0 = 0; float l0 = acc[0];
#pragma unroll
        for (int e = 1; e < NE; e++) if (acc[e] > l0) { l0 = acc[e]; i0 = e; }
        int i1 = -1; float l1 = -1e30f;
#pragma unroll
        for (int e = 0; e < NE; e++) if (e != i0 && acc[e] > l1) { l1 = acc[e]; i1 = e; }
        float ex = __expf(l1 - l0);
        float w0 = 1.f / (1.f + ex);
        float w1 = ex * w0;
        g_w2[2 * t] = w0;
        g_w2[2 * t + 1] = w1;
        int s0 = atomicAdd(&g_cnt[i0], 1);
        g_tokp[i0 * TOK + s0] = t;                          // k = 0
        int s1 = atomicAdd(&g_cnt[i1], 1);
        g_tokp[i1 * TOK + s1] = t | 0x80000000;             // k = 1
    }
}

// ---------------- GEMM1: h = silu(x@Wg)*(x@Wu); 128x128x64, 8 warps 64x32 -------
struct SmemG1 {
    __half A[3][BM][A_ST];     // 55296 B
    __half Bg[3][BK][B1_ST];   // 52224 B
    __half Bu[3][BK][B1_ST];   // 52224 B
    int    tok[BM];
};                             // ~160 KB -> 1 CTA/SM, regs uncapped

__device__ __forceinline__ void g1_load(SmemG1* s, int st, int k0,
                                        const int* tok_s, int e, int n_base, int tid) {
#pragma unroll
    for (int i = 0; i < 4; i++) {                 // A: 128 rows x 8 chunks(16B)
        int idx = tid + i * 256;
        int row = idx >> 3, c = idx & 7;
        cp16(saddr(&s->A[st][row][c * 8]), &g_xh[(size_t)tok_s[row] * HD + k0 + c * 8]);
    }
    const __half* bg = g_wgh + ((size_t)e * HD + k0) * ID + n_base;
    const __half* bu = g_wuh + ((size_t)e * HD + k0) * ID + n_base;
#pragma unroll
    for (int i = 0; i < 4; i++) {                 // Bg/Bu: 64 rows x 16 chunks
        int idx = tid + i * 256;
        int kr = idx >> 4, c = idx & 15;
        cp16(saddr(&s->Bg[st][kr][c * 8]), bg + (size_t)kr * ID + c * 8);
        cp16(saddr(&s->Bu[st][kr][c * 8]), bu + (size_t)kr * ID + c * 8);
    }
}

#define KT1 (HD / BK)   // 32

__global__ void __launch_bounds__(256) gemm1_kernel() {
    extern __shared__ __align__(16) char smem_raw[];
    SmemG1* s = (SmemG1*)smem_raw;

    int e = blockIdx.z;
    int cnt = g_cnt[e];
    int m_base = blockIdx.y * BM;
    if (m_base >= cnt) return;
    int n_base = blockIdx.x * BN1;
    int tid = threadIdx.x;

    if (tid < BM) {
        int m = m_base + tid;
        s->tok[tid] = (m < cnt) ? (g_tokp[e * TOK + m] & 0x7fffffff) : 0;
    }
    __syncthreads();

    int wid = tid >> 5, lane = tid & 31;
    int wm = wid >> 2, wn = wid & 3;               // 2 x 4 warps, warp 64x32
    int r = lane >> 2, cq = lane & 3;
    int lrow = lane & 15, lcol = (lane >> 4) << 3;

    float acc_g[4][4][4], acc_u[4][4][4];
#pragma unroll
    for (int mf = 0; mf < 4; mf++)
#pragma unroll
        for (int nf = 0; nf < 4; nf++)
#pragma unroll
            for (int k = 0; k < 4; k++) { acc_g[mf][nf][k] = 0.f; acc_u[mf][nf][k] = 0.f; }

    g1_load(s, 0, 0, s->tok, e, n_base, tid);  cp_commit();
    g1_load(s, 1, BK, s->tok, e, n_base, tid); cp_commit();

    for (int kt = 0; kt < KT1; kt++) {
        cp_wait<1>();
        __syncthreads();
        int nxt = kt + 2;
        if (nxt < KT1) g1_load(s, nxt % 3, nxt * BK, s->tok, e, n_base, tid);
        cp_commit();

        int sg = kt % 3;
        uint32_t sA  = saddr(&s->A[sg][0][0]);
        uint32_t sBg = saddr(&s->Bg[sg][0][0]);
        uint32_t sBu = saddr(&s->Bu[sg][0][0]);
#pragma unroll
        for (int ks = 0; ks < BK / 16; ks++) {
            int k16 = ks * 16;
            uint32_t a[4][4];
#pragma unroll
            for (int mf = 0; mf < 4; mf++)
                ldsm_x4(a[mf], sA + 2 * ((wm * 64 + mf * 16 + lrow) * A_ST + k16 + lcol));
            uint32_t bg[2][4], bu[2][4];
#pragma unroll
            for (int ng = 0; ng < 2; ng++) {
                uint32_t off = 2 * ((k16 + lrow) * B1_ST + wn * 32 + ng * 16 + lcol);
                ldsm_x4t(bg[ng], sBg + off);
                ldsm_x4t(bu[ng], sBu + off);
            }
#pragma unroll
            for (int mf = 0; mf < 4; mf++)
#pragma unroll
                for (int nf = 0; nf < 4; nf++) {
                    mma_f16(acc_g[mf][nf], a[mf], &bg[nf >> 1][(nf & 1) * 2]);
                    mma_f16(acc_u[mf][nf], a[mf], &bu[nf >> 1][(nf & 1) * 2]);
                }
        }
    }

    // epilogue: silu(g)*u -> fp16 -> g_hh
#pragma unroll
    for (int mf = 0; mf < 4; mf++) {
#pragma unroll
        for (int nf = 0; nf < 4; nf++) {
            int rl = wm * 64 + mf * 16 + r;
            int col = n_base + wn * 32 + nf * 8 + cq * 2;
            if (m_base + rl < cnt) {
                float g0 = acc_g[mf][nf][0], u0 = acc_u[mf][nf][0];
                float g1 = acc_g[mf][nf][1], u1 = acc_u[mf][nf][1];
                float v0 = (g0 / (1.f + __expf(-g0))) * u0;
                float v1 = (g1 / (1.f + __expf(-g1))) * u1;
                __half2* p = (__half2*)&g_hh[((size_t)e * TOK + m_base + rl) * ID + col];
                *p = __floats2half2_rn(v0, v1);
            }
            if (m_base + rl + 8 < cnt) {
                float g0 = acc_g[mf][nf][2], u0 = acc_u[mf][nf][2];
                float g1 = acc_g[mf][nf][3], u1 = acc_u[mf][nf][3];
                float v0 = (g0 / (1.f + __expf(-g0))) * u0;
                float v1 = (g1 / (1.f + __expf(-g1))) * u1;
                __half2* p = (__half2*)&g_hh[((size_t)e * TOK + m_base + rl + 8) * ID + col];
                *p = __floats2half2_rn(v0, v1);
            }
        }
    }
}

// ---------------- GEMM2: y = h @ Wd; 128x256x64, 8 warps 64x64 ------------------
struct SmemG2 {
    __half A[3][BM][A_ST];     // 55296 B
    __half B[3][BK][B2_ST];    // 101376 B
    int    tokp[BM];
};                             // ~157 KB -> 1 CTA/SM, regs uncapped

__device__ __forceinline__ void g2_load(SmemG2* s, int st, int k0,
                                        int e, int m_base, int n_base, int tid) {
    const __half* arow = g_hh + ((size_t)e * TOK + m_base) * ID + k0;
    const __half* brow = g_wdh + ((size_t)e * ID + k0) * HD + n_base;
#pragma unroll
    for (int i = 0; i < 4; i++) {                 // A: 1024 chunks
        int idx = tid + i * 256;
        int row = idx >> 3, c = idx & 7;
        cp16(saddr(&s->A[st][row][c * 8]), arow + (size_t)row * ID + c * 8);
    }
#pragma unroll
    for (int i = 0; i < 8; i++) {                 // B: 64 rows x 32 chunks = 2048
        int idx = tid + i * 256;
        int kr = idx >> 5, c = idx & 31;
        cp16(saddr(&s->B[st][kr][c * 8]), brow + (size_t)kr * HD + c * 8);
    }
}

#define KT2 (ID / BK)   // 22

__global__ void __launch_bounds__(256) gemm2_kernel() {
    extern __shared__ __align__(16) char smem_raw[];
    SmemG2* s = (SmemG2*)smem_raw;

    int e = blockIdx.z;
    int cnt = g_cnt[e];
    int m_base = blockIdx.y * BM;
    if (m_base >= cnt) return;
    int n_base = blockIdx.x * BN2;
    int tid = threadIdx.x;

    if (tid < BM) {
        int m = m_base + tid;
        s->tokp[tid] = (m < cnt) ? g_tokp[e * TOK + m] : 0;
    }
    __syncthreads();

    int wid = tid >> 5, lane = tid & 31;
    int wm = wid >> 2, wn = wid & 3;               // 2 x 4 warps, warp 64x64
    int r = lane >> 2, cq = lane & 3;
    int lrow = lane & 15, lcol = (lane >> 4) << 3;

    float acc[4][8][4];
#pragma unroll
    for (int mf = 0; mf < 4; mf++)
#pragma unroll
        for (int nf = 0; nf < 8; nf++)
#pragma unroll
            for (int k = 0; k < 4; k++) acc[mf][nf][k] = 0.f;

    g2_load(s, 0, 0, e, m_base, n_base, tid);  cp_commit();
    g2_load(s, 1, BK, e, m_base, n_base, tid); cp_commit();

    for (int kt = 0; kt < KT2; kt++) {
        cp_wait<1>();
        __syncthreads();
        int nxt = kt + 2;
        if (nxt < KT2) g2_load(s, nxt % 3, nxt * BK, e, m_base, n_base, tid);
        cp_commit();

        int sg = kt % 3;
        uint32_t sA = saddr(&s->A[sg][0][0]);
        uint32_t sB = saddr(&s->B[sg][0][0]);
#pragma unroll
        for (int ks = 0; ks < BK / 16; ks++) {
            int k16 = ks * 16;
            uint32_t a[4][4];
#pragma unroll
            for (int mf = 0; mf < 4; mf++)
                ldsm_x4(a[mf], sA + 2 * ((wm * 64 + mf * 16 + lrow) * A_ST + k16 + lcol));
            uint32_t b[4][4];
#pragma unroll
            for (int ng = 0; ng < 4; ng++) {
                uint32_t off = 2 * ((k16 + lrow) * B2_ST + wn * 64 + ng * 16 + lcol);
                ldsm_x4t(b[ng], sB + off);
            }
#pragma unroll
            for (int mf = 0; mf < 4; mf++)
#pragma unroll
                for (int nf = 0; nf < 8; nf++)
                    mma_f16(acc[mf][nf], a[mf], &b[nf >> 1][(nf & 1) * 2]);
        }
    }

    // epilogue: plain stores to g_y[k][t]
#pragma unroll
    for (int mf = 0; mf < 4; mf++) {
#pragma unroll
        for (int nf = 0; nf < 8; nf++) {
            int rl = wm * 64 + mf * 16 + r;
            int col = n_base + wn * 64 + nf * 8 + cq * 2;
            if (m_base + rl < cnt) {
                int pk = s->tokp[rl];
                int t = pk & 0x7fffffff;
                int k = (uint32_t)pk >> 31;
                float2* p = (float2*)&g_y[((size_t)k * TOK + t) * HD + col];
                *p = make_float2(acc[mf][nf][0], acc[mf][nf][1]);
            }
            if (m_base + rl + 8 < cnt) {
                int pk = s->tokp[rl + 8];
                int t = pk & 0x7fffffff;
                int k = (uint32_t)pk >> 31;
                float2* p = (float2*)&g_y[((size_t)k * TOK + t) * HD + col];
                *p = make_float2(acc[mf][nf][2], acc[mf][nf][3]);
            }
        }
    }
}

// ---------------- combine: out = w0*y0 + w1*y1 ----------------------------------
__global__ void combine_kernel(float4* __restrict__ out) {
    const int n4 = TOK * HD / 4;
    const float4* y0 = (const float4*)g_y;
    const float4* y1 = y0 + n4;
    for (int i = blockIdx.x * blockDim.x + threadIdx.x; i < n4; i += gridDim.x * blockDim.x) {
        int t = i / (HD / 4);
        float w0 = g_w2[2 * t], w1 = g_w2[2 * t + 1];
        float4 a = y0[i], b = y1[i];
        float4 o;
        o.x = w0 * a.x + w1 * b.x;
        o.y = w0 * a.y + w1 * b.y;
        o.z = w0 * a.z + w1 * b.z;
        o.w = w0 * a.w + w1 * b.w;
        out[i] = o;
    }
}

// ---------------- host launcher -------------------------------------------------
extern "C" void kernel_launch(void* const* d_in, const int* in_sizes, int n_in,
                              void* d_out, int out_size) {
    const float* x  = (const float*)d_in[0];
    const float* gw = (const float*)d_in[1];
    const float* wg = (const float*)d_in[2];
    const float* wu = (const float*)d_in[3];
    const float* wd = (const float*)d_in[4];
    (void)in_sizes; (void)n_in; (void)out_size;

    zero_cnt_kernel<<<1, 32>>>();

    {
        dim3 grid(1024, 1, 3);
        conv_half_kernel<<<grid, 256>>>((const float4*)wg, (const float4*)wu,
                                        (const float4*)wd);
    }

    cudaFuncSetAttribute(router_kernel, cudaFuncAttributeMaxDynamicSharedMemorySize,
                         NE * HD * (int)sizeof(float));
    router_kernel<<<TOK * 32 / 256, 256, NE * HD * sizeof(float)>>>(x, gw);

    cudaFuncSetAttribute(gemm1_kernel, cudaFuncAttributeMaxDynamicSharedMemorySize,
                         (int)sizeof(SmemG1));
    dim3 grid1(ID / BN1, TOK / BM, NE);     // 11 x 64 x 8
    gemm1_kernel<<<grid1, 256, sizeof(SmemG1)>>>();

    cudaFuncSetAttribute(gemm2_kernel, cudaFuncAttributeMaxDynamicSharedMemorySize,
                         (int)sizeof(SmemG2));
    dim3 grid2(HD / BN2, TOK / BM, NE);     // 8 x 64 x 8
    gemm2_kernel<<<grid2, 256, sizeof(SmemG2)>>>();

    combine_kernel<<<2048, 256>>>((float4*)d_out);
}

// round 7
// speedup vs baseline: 2.0795x; 1.0021x over previous
#include <cuda_runtime.h>
#include <cuda_fp16.h>
#include <cstdint>

#define TOK 8192
#define HD  2048
#define ID  1408
#define NE  8

#define BM   128
#define BK   64
#define BN1  128
#define BN2  256
#define A_ST 72      // 64 + 8 halves -> 144B row stride
#define B1_ST 136    // 128 + 8 halves -> 272B
#define B2_ST 264    // 256 + 8 halves -> 528B

// ---------------- device scratch (no allocations allowed) ----------------------
__device__ __half g_xh[(size_t)TOK * HD];       // fp16 x
__device__ __half g_wgh[(size_t)NE * HD * ID];  // fp16 weights, native [k][n]
__device__ __half g_wuh[(size_t)NE * HD * ID];
__device__ __half g_wdh[(size_t)NE * ID * HD];
__device__ int    g_cnt[NE];
__device__ int    g_tokp[NE * TOK];             // token | (k<<31)
__device__ float  g_w2[TOK * 2];                // per-token (w0, w1)
__device__ __half g_hh[(size_t)NE * TOK * ID];  // fp16 intermediate (slot-indexed)
__device__ float  g_y[(size_t)2 * TOK * HD];    // unweighted expert outputs per k

// ---------------- helpers ------------------------------------------------------
__device__ __forceinline__ uint32_t saddr(const void* p) {
    return (uint32_t)__cvta_generic_to_shared(p);
}
__device__ __forceinline__ void cp16(uint32_t dst, const void* src) {
    asm volatile("cp.async.cg.shared.global [%0], [%1], 16;" :: "r"(dst), "l"(src));
}
__device__ __forceinline__ void cp_commit() { asm volatile("cp.async.commit_group;"); }
template <int N>
__device__ __forceinline__ void cp_wait() { asm volatile("cp.async.wait_group %0;" :: "n"(N)); }

__device__ __forceinline__ void ldsm_x4(uint32_t* r, uint32_t addr) {
    asm volatile("ldmatrix.sync.aligned.m8n8.x4.shared.b16 {%0,%1,%2,%3}, [%4];"
                 : "=r"(r[0]), "=r"(r[1]), "=r"(r[2]), "=r"(r[3]) : "r"(addr));
}
__device__ __forceinline__ void ldsm_x4t(uint32_t* r, uint32_t addr) {
    asm volatile("ldmatrix.sync.aligned.m8n8.x4.trans.shared.b16 {%0,%1,%2,%3}, [%4];"
                 : "=r"(r[0]), "=r"(r[1]), "=r"(r[2]), "=r"(r[3]) : "r"(addr));
}
__device__ __forceinline__ void mma_f16(float d[4], const uint32_t a[4], const uint32_t b[2]) {
    asm volatile(
        "mma.sync.aligned.m16n8k16.row.col.f32.f16.f16.f32 "
        "{%0,%1,%2,%3}, {%4,%5,%6,%7}, {%8,%9}, {%0,%1,%2,%3};"
        : "+f"(d[0]), "+f"(d[1]), "+f"(d[2]), "+f"(d[3])
        : "r"(a[0]), "r"(a[1]), "r"(a[2]), "r"(a[3]), "r"(b[0]), "r"(b[1]));
}

// ---------------- small kernels ------------------------------------------------
__global__ void zero_cnt_kernel() {
    if (threadIdx.x < NE) g_cnt[threadIdx.x] = 0;
}

// single conv pass for all 3 weight tensors (blockIdx.z selects)
__global__ void conv_half_kernel(const float4* __restrict__ wg,
                                 const float4* __restrict__ wu,
                                 const float4* __restrict__ wd) {
    const int n4 = NE * HD * ID / 4;
    const float4* in = blockIdx.z == 0 ? wg : blockIdx.z == 1 ? wu : wd;
    uint2* out = (uint2*)(blockIdx.z == 0 ? g_wgh : blockIdx.z == 1 ? g_wuh : g_wdh);
    for (int i = blockIdx.x * blockDim.x + threadIdx.x; i < n4; i += gridDim.x * blockDim.x) {
        float4 v = in[i];
        __half2 lo = __floats2half2_rn(v.x, v.y);
        __half2 hi = __floats2half2_rn(v.z, v.w);
        uint2 o;
        o.x = *(uint32_t*)&lo;
        o.y = *(uint32_t*)&hi;
        out[i] = o;
    }
}

// Router + fused fp16 conversion of x. One warp per token.
__global__ void router_kernel(const float* __restrict__ x, const float* __restrict__ gw) {
    extern __shared__ float s_gw[];  // NE*HD = 64 KB
    for (int i = threadIdx.x; i < NE * HD; i += blockDim.x) s_gw[i] = gw[i];
    __syncthreads();

    int gtid = blockIdx.x * blockDim.x + threadIdx.x;
    int t = gtid >> 5, lane = gtid & 31;
    if (t >= TOK) return;

    float acc[NE];
#pragma unroll
    for (int e = 0; e < NE; e++) acc[e] = 0.f;

    const float* xr = x + (size_t)t * HD;
    __half* xo = g_xh + (size_t)t * HD;
    for (int i = lane; i < HD; i += 32) {
        float xv = xr[i];
        xo[i] = __float2half_rn(xv);
#pragma unroll
        for (int e = 0; e < NE; e++) acc[e] += xv * s_gw[e * HD + i];
    }
#pragma unroll
    for (int e = 0; e < NE; e++) {
#pragma unroll
        for (int off = 16; off > 0; off >>= 1)
            acc[e] += __shfl_xor_sync(0xffffffffu, acc[e], off);
    }
    if (lane == 0) {
        int i0 = 0; float l0 = acc[0];
#pragma unroll
        for (int e = 1; e < NE; e++) if (acc[e] > l0) { l0 = acc[e]; i0 = e; }
        int i1 = -1; float l1 = -1e30f;
#pragma unroll
        for (int e = 0; e < NE; e++) if (e != i0 && acc[e] > l1) { l1 = acc[e]; i1 = e; }
        float ex = __expf(l1 - l0);
        float w0 = 1.f / (1.f + ex);
        float w1 = ex * w0;
        g_w2[2 * t] = w0;
        g_w2[2 * t + 1] = w1;
        int s0 = atomicAdd(&g_cnt[i0], 1);
        g_tokp[i0 * TOK + s0] = t;                          // k = 0
        int s1 = atomicAdd(&g_cnt[i1], 1);
        g_tokp[i1 * TOK + s1] = t | 0x80000000;             // k = 1
    }
}

// ---------------- GEMM1: h = silu(x@Wg)*(x@Wu); 128x128x64, 8 warps 64x32 -------
struct SmemG1 {
    __half A[3][BM][A_ST];     // 55296 B
    __half Bg[3][BK][B1_ST];   // 52224 B
    __half Bu[3][BK][B1_ST];   // 52224 B
    int    tok[BM];
};                             // ~160 KB -> 1 CTA/SM, regs uncapped

__device__ __forceinline__ void g1_load(SmemG1* s, int st, int k0,
                                        const int* tok_s, int e, int n_base, int tid) {
#pragma unroll
    for (int i = 0; i < 4; i++) {                 // A: 128 rows x 8 chunks(16B)
        int idx = tid + i * 256;
        int row = idx >> 3, c = idx & 7;
        cp16(saddr(&s->A[st][row][c * 8]), &g_xh[(size_t)tok_s[row] * HD + k0 + c * 8]);
    }
    const __half* bg = g_wgh + ((size_t)e * HD + k0) * ID + n_base;
    const __half* bu = g_wuh + ((size_t)e * HD + k0) * ID + n_base;
#pragma unroll
    for (int i = 0; i < 4; i++) {                 // Bg/Bu: 64 rows x 16 chunks
        int idx = tid + i * 256;
        int kr = idx >> 4, c = idx & 15;
        cp16(saddr(&s->Bg[st][kr][c * 8]), bg + (size_t)kr * ID + c * 8);
        cp16(saddr(&s->Bu[st][kr][c * 8]), bu + (size_t)kr * ID + c * 8);
    }
}

__device__ __forceinline__ void g1_frags(uint32_t sA, uint32_t sBg, uint32_t sBu,
                                         int k16, int wm, int wn, int lrow, int lcol,
                                         uint32_t a[4][4], uint32_t bg[2][4],
                                         uint32_t bu[2][4]) {
#pragma unroll
    for (int mf = 0; mf < 4; mf++)
        ldsm_x4(a[mf], sA + 2 * ((wm * 64 + mf * 16 + lrow) * A_ST + k16 + lcol));
#pragma unroll
    for (int ng = 0; ng < 2; ng++) {
        uint32_t off = 2 * ((k16 + lrow) * B1_ST + wn * 32 + ng * 16 + lcol);
        ldsm_x4t(bg[ng], sBg + off);
        ldsm_x4t(bu[ng], sBu + off);
    }
}

#define KT1 (HD / BK)   // 32

__global__ void __launch_bounds__(256) gemm1_kernel() {
    extern __shared__ __align__(16) char smem_raw[];
    SmemG1* s = (SmemG1*)smem_raw;

    int e = blockIdx.z;
    int cnt = g_cnt[e];
    int m_base = blockIdx.y * BM;
    if (m_base >= cnt) return;
    int n_base = blockIdx.x * BN1;
    int tid = threadIdx.x;

    if (tid < BM) {
        int m = m_base + tid;
        s->tok[tid] = (m < cnt) ? (g_tokp[e * TOK + m] & 0x7fffffff) : 0;
    }
    __syncthreads();

    int wid = tid >> 5, lane = tid & 31;
    int wm = wid >> 2, wn = wid & 3;               // 2 x 4 warps, warp 64x32
    int r = lane >> 2, cq = lane & 3;
    int lrow = lane & 15, lcol = (lane >> 4) << 3;

    float acc_g[4][4][4], acc_u[4][4][4];
#pragma unroll
    for (int mf = 0; mf < 4; mf++)
#pragma unroll
        for (int nf = 0; nf < 4; nf++)
#pragma unroll
            for (int k = 0; k < 4; k++) { acc_g[mf][nf][k] = 0.f; acc_u[mf][nf][k] = 0.f; }

    g1_load(s, 0, 0, s->tok, e, n_base, tid);  cp_commit();
    g1_load(s, 1, BK, s->tok, e, n_base, tid); cp_commit();

    uint32_t af[2][4][4], bgf[2][2][4], buf2[2][2][4];

    for (int kt = 0; kt < KT1; kt++) {
        cp_wait<1>();
        __syncthreads();
        int nxt = kt + 2;
        if (nxt < KT1) g1_load(s, nxt % 3, nxt * BK, s->tok, e, n_base, tid);
        cp_commit();

        int sg = kt % 3;
        uint32_t sA  = saddr(&s->A[sg][0][0]);
        uint32_t sBg = saddr(&s->Bg[sg][0][0]);
        uint32_t sBu = saddr(&s->Bu[sg][0][0]);

        // fragment double-buffer: prefetch ks+1 while issuing mma for ks
        g1_frags(sA, sBg, sBu, 0, wm, wn, lrow, lcol, af[0], bgf[0], buf2[0]);
#pragma unroll
        for (int ks = 0; ks < BK / 16; ks++) {
            int cur = ks & 1;
            if (ks + 1 < BK / 16)
                g1_frags(sA, sBg, sBu, (ks + 1) * 16, wm, wn, lrow, lcol,
                         af[cur ^ 1], bgf[cur ^ 1], buf2[cur ^ 1]);
#pragma unroll
            for (int mf = 0; mf < 4; mf++)
#pragma unroll
                for (int nf = 0; nf < 4; nf++) {
                    mma_f16(acc_g[mf][nf], af[cur][mf], &bgf[cur][nf >> 1][(nf & 1) * 2]);
                    mma_f16(acc_u[mf][nf], af[cur][mf], &buf2[cur][nf >> 1][(nf & 1) * 2]);
                }
        }
    }

    // epilogue: silu(g)*u -> fp16 -> g_hh
#pragma unroll
    for (int mf = 0; mf < 4; mf++) {
#pragma unroll
        for (int nf = 0; nf < 4; nf++) {
            int rl = wm * 64 + mf * 16 + r;
            int col = n_base + wn * 32 + nf * 8 + cq * 2;
            if (m_base + rl < cnt) {
                float g0 = acc_g[mf][nf][0], u0 = acc_u[mf][nf][0];
                float g1 = acc_g[mf][nf][1], u1 = acc_u[mf][nf][1];
                float v0 = (g0 / (1.f + __expf(-g0))) * u0;
                float v1 = (g1 / (1.f + __expf(-g1))) * u1;
                __half2* p = (__half2*)&g_hh[((size_t)e * TOK + m_base + rl) * ID + col];
                *p = __floats2half2_rn(v0, v1);
            }
            if (m_base + rl + 8 < cnt) {
                float g0 = acc_g[mf][nf][2], u0 = acc_u[mf][nf][2];
                float g1 = acc_g[mf][nf][3], u1 = acc_u[mf][nf][3];
                float v0 = (g0 / (1.f + __expf(-g0))) * u0;
                float v1 = (g1 / (1.f + __expf(-g1))) * u1;
                __half2* p = (__half2*)&g_hh[((size_t)e * TOK + m_base + rl + 8) * ID + col];
                *p = __floats2half2_rn(v0, v1);
            }
        }
    }
}

// ---------------- GEMM2: y = h @ Wd; 128x256x64, 8 warps 64x64 ------------------
struct SmemG2 {
    __half A[3][BM][A_ST];     // 55296 B
    __half B[3][BK][B2_ST];    // 101376 B
    int    tokp[BM];
};                             // ~157 KB -> 1 CTA/SM, regs uncapped

__device__ __forceinline__ void g2_load(SmemG2* s, int st, int k0,
                                        int e, int m_base, int n_base, int tid) {
    const __half* arow = g_hh + ((size_t)e * TOK + m_base) * ID + k0;
    const __half* brow = g_wdh + ((size_t)e * ID + k0) * HD + n_base;
#pragma unroll
    for (int i = 0; i < 4; i++) {                 // A: 1024 chunks
        int idx = tid + i * 256;
        int row = idx >> 3, c = idx & 7;
        cp16(saddr(&s->A[st][row][c * 8]), arow + (size_t)row * ID + c * 8);
    }
#pragma unroll
    for (int i = 0; i < 8; i++) {                 // B: 64 rows x 32 chunks = 2048
        int idx = tid + i * 256;
        int kr = idx >> 5, c = idx & 31;
        cp16(saddr(&s->B[st][kr][c * 8]), brow + (size_t)kr * HD + c * 8);
    }
}

__device__ __forceinline__ void g2_frags(uint32_t sA, uint32_t sB, int k16,
                                         int wm, int wn, int lrow, int lcol,
                                         uint32_t a[4][4], uint32_t b[4][4]) {
#pragma unroll
    for (int mf = 0; mf < 4; mf++)
        ldsm_x4(a[mf], sA + 2 * ((wm * 64 + mf * 16 + lrow) * A_ST + k16 + lcol));
#pragma unroll
    for (int ng = 0; ng < 4; ng++) {
        uint32_t off = 2 * ((k16 + lrow) * B2_ST + wn * 64 + ng * 16 + lcol);
        ldsm_x4t(b[ng], sB + off);
    }
}

#define KT2 (ID / BK)   // 22

__global__ void __launch_bounds__(256) gemm2_kernel() {
    extern __shared__ __align__(16) char smem_raw[];
    SmemG2* s = (SmemG2*)smem_raw;

    int e = blockIdx.z;
    int cnt = g_cnt[e];
    int m_base = blockIdx.y * BM;
    if (m_base >= cnt) return;
    int n_base = blockIdx.x * BN2;
    int tid = threadIdx.x;

    if (tid < BM) {
        int m = m_base + tid;
        s->tokp[tid] = (m < cnt) ? g_tokp[e * TOK + m] : 0;
    }
    __syncthreads();

    int wid = tid >> 5, lane = tid & 31;
    int wm = wid >> 2, wn = wid & 3;               // 2 x 4 warps, warp 64x64
    int r = lane >> 2, cq = lane & 3;
    int lrow = lane & 15, lcol = (lane >> 4) << 3;

    float acc[4][8][4];
#pragma unroll
    for (int mf = 0; mf < 4; mf++)
#pragma unroll
        for (int nf = 0; nf < 8; nf++)
#pragma unroll
            for (int k = 0; k < 4; k++) acc[mf][nf][k] = 0.f;

    g2_load(s, 0, 0, e, m_base, n_base, tid);  cp_commit();
    g2_load(s, 1, BK, e, m_base, n_base, tid); cp_commit();

    uint32_t af[2][4][4], bf[2][4][4];

    for (int kt = 0; kt < KT2; kt++) {
        cp_wait<1>();
        __syncthreads();
        int nxt = kt + 2;
        if (nxt < KT2) g2_load(s, nxt % 3, nxt * BK, e, m_base, n_base, tid);
        cp_commit();

        int sg = kt % 3;
        uint32_t sA = saddr(&s->A[sg][0][0]);
        uint32_t sB = saddr(&s->B[sg][0][0]);

        g2_frags(sA, sB, 0, wm, wn, lrow, lcol, af[0], bf[0]);
#pragma unroll
        for (int ks = 0; ks < BK / 16; ks++) {
            int cur = ks & 1;
            if (ks + 1 < BK / 16)
                g2_frags(sA, sB, (ks + 1) * 16, wm, wn, lrow, lcol,
                         af[cur ^ 1], bf[cur ^ 1]);
#pragma unroll
            for (int mf = 0; mf < 4; mf++)
#pragma unroll
                for (int nf = 0; nf < 8; nf++)
                    mma_f16(acc[mf][nf], af[cur][mf], &bf[cur][nf >> 1][(nf & 1) * 2]);
        }
    }

    // epilogue: plain stores to g_y[k][t]
#pragma unroll
    for (int mf = 0; mf < 4; mf++) {
#pragma unroll
        for (int nf = 0; nf < 8; nf++) {
            int rl = wm * 64 + mf * 16 + r;
            int col = n_base + wn * 64 + nf * 8 + cq * 2;
            if (m_base + rl < cnt) {
                int pk = s->tokp[rl];
                int t = pk & 0x7fffffff;
                int k = (uint32_t)pk >> 31;
                float2* p = (float2*)&g_y[((size_t)k * TOK + t) * HD + col];
                *p = make_float2(acc[mf][nf][0], acc[mf][nf][1]);
            }
            if (m_base + rl + 8 < cnt) {
                int pk = s->tokp[rl + 8];
                int t = pk & 0x7fffffff;
                int k = (uint32_t)pk >> 31;
                float2* p = (float2*)&g_y[((size_t)k * TOK + t) * HD + col];
                *p = make_float2(acc[mf][nf][2], acc[mf][nf][3]);
            }
        }
    }
}

// ---------------- combine: out = w0*y0 + w1*y1 ----------------------------------
__global__ void combine_kernel(float4* __restrict__ out) {
    const int n4 = TOK * HD / 4;
    const float4* y0 = (const float4*)g_y;
    const float4* y1 = y0 + n4;
    for (int i = blockIdx.x * blockDim.x + threadIdx.x; i < n4; i += gridDim.x * blockDim.x) {
        int t = i / (HD / 4);
        float w0 = g_w2[2 * t], w1 = g_w2[2 * t + 1];
        float4 a = y0[i], b = y1[i];
        float4 o;
        o.x = w0 * a.x + w1 * b.x;
        o.y = w0 * a.y + w1 * b.y;
        o.z = w0 * a.z + w1 * b.z;
        o.w = w0 * a.w + w1 * b.w;
        out[i] = o;
    }
}

// ---------------- host launcher -------------------------------------------------
extern "C" void kernel_launch(void* const* d_in, const int* in_sizes, int n_in,
                              void* d_out, int out_size) {
    const float* x  = (const float*)d_in[0];
    const float* gw = (const float*)d_in[1];
    const float* wg = (const float*)d_in[2];
    const float* wu = (const float*)d_in[3];
    const float* wd = (const float*)d_in[4];
    (void)in_sizes; (void)n_in; (void)out_size;

    zero_cnt_kernel<<<1, 32>>>();

    {
        dim3 grid(1024, 1, 3);
        conv_half_kernel<<<grid, 256>>>((const float4*)wg, (const float4*)wu,
                                        (const float4*)wd);
    }

    cudaFuncSetAttribute(router_kernel, cudaFuncAttributeMaxDynamicSharedMemorySize,
                         NE * HD * (int)sizeof(float));
    router_kernel<<<TOK * 32 / 256, 256, NE * HD * sizeof(float)>>>(x, gw);

    cudaFuncSetAttribute(gemm1_kernel, cudaFuncAttributeMaxDynamicSharedMemorySize,
                         (int)sizeof(SmemG1));
    dim3 grid1(ID / BN1, TOK / BM, NE);     // 11 x 64 x 8
    gemm1_kernel<<<grid1, 256, sizeof(SmemG1)>>>();

    cudaFuncSetAttribute(gemm2_kernel, cudaFuncAttributeMaxDynamicSharedMemorySize,
                         (int)sizeof(SmemG2));
    dim3 grid2(HD / BN2, TOK / BM, NE);     // 8 x 64 x 8
    gemm2_kernel<<<grid2, 256, sizeof(SmemG2)>>>();

    combine_kernel<<<2048, 256>>>((float4*)d_out);
}

// round 8
// speedup vs baseline: 2.1019x; 1.0108x over previous
#include <cuda_runtime.h>
#include <cuda_fp16.h>
#include <cstdint>

#define TOK 8192
#define HD  2048
#define ID  1408
#define NE  8

#define BM   192
#define BK   64
#define BN1  128
#define BN2  256
#define NTHR 384
#define MBLK 43      // ceil(TOK / BM)
#define A_ST 72      // 64 + 8 halves -> 144B row stride
#define B1_ST 136    // 128 + 8 halves -> 272B
#define B2_ST 264    // 256 + 8 halves -> 528B

// ---------------- device scratch (no allocations allowed) ----------------------
__device__ __half g_xh[(size_t)TOK * HD];       // fp16 x
__device__ __half g_wgh[(size_t)NE * HD * ID];  // fp16 weights, native [k][n]
__device__ __half g_wuh[(size_t)NE * HD * ID];
__device__ __half g_wdh[(size_t)NE * ID * HD];
__device__ int    g_cnt[NE];
__device__ int    g_tokp[NE * TOK];             // token | (k<<31)
__device__ float  g_w2[TOK * 2];                // per-token (w0, w1)
__device__ __half g_hh[(size_t)NE * TOK * ID];  // fp16 intermediate (slot-indexed)
__device__ float  g_y[(size_t)2 * TOK * HD];    // unweighted expert outputs per k

// ---------------- helpers ------------------------------------------------------
__device__ __forceinline__ uint32_t saddr(const void* p) {
    return (uint32_t)__cvta_generic_to_shared(p);
}
__device__ __forceinline__ void cp16(uint32_t dst, const void* src) {
    asm volatile("cp.async.cg.shared.global [%0], [%1], 16;" :: "r"(dst), "l"(src));
}
__device__ __forceinline__ void cp_commit() { asm volatile("cp.async.commit_group;"); }
template <int N>
__device__ __forceinline__ void cp_wait() { asm volatile("cp.async.wait_group %0;" :: "n"(N)); }

__device__ __forceinline__ void ldsm_x4(uint32_t* r, uint32_t addr) {
    asm volatile("ldmatrix.sync.aligned.m8n8.x4.shared.b16 {%0,%1,%2,%3}, [%4];"
                 : "=r"(r[0]), "=r"(r[1]), "=r"(r[2]), "=r"(r[3]) : "r"(addr));
}
__device__ __forceinline__ void ldsm_x4t(uint32_t* r, uint32_t addr) {
    asm volatile("ldmatrix.sync.aligned.m8n8.x4.trans.shared.b16 {%0,%1,%2,%3}, [%4];"
                 : "=r"(r[0]), "=r"(r[1]), "=r"(r[2]), "=r"(r[3]) : "r"(addr));
}
__device__ __forceinline__ void mma_f16(float d[4], const uint32_t a[4], const uint32_t b[2]) {
    asm volatile(
        "mma.sync.aligned.m16n8k16.row.col.f32.f16.f16.f32 "
        "{%0,%1,%2,%3}, {%4,%5,%6,%7}, {%8,%9}, {%0,%1,%2,%3};"
        : "+f"(d[0]), "+f"(d[1]), "+f"(d[2]), "+f"(d[3])
        : "r"(a[0]), "r"(a[1]), "r"(a[2]), "r"(a[3]), "r"(b[0]), "r"(b[1]));
}

// ---------------- small kernels ------------------------------------------------
__global__ void zero_cnt_kernel() {
    if (threadIdx.x < NE) g_cnt[threadIdx.x] = 0;
}

// single conv pass for all 3 weight tensors (blockIdx.z selects)
__global__ void conv_half_kernel(const float4* __restrict__ wg,
                                 const float4* __restrict__ wu,
                                 const float4* __restrict__ wd) {
    const int n4 = NE * HD * ID / 4;
    const float4* in = blockIdx.z == 0 ? wg : blockIdx.z == 1 ? wu : wd;
    uint2* out = (uint2*)(blockIdx.z == 0 ? g_wgh : blockIdx.z == 1 ? g_wuh : g_wdh);
    for (int i = blockIdx.x * blockDim.x + threadIdx.x; i < n4; i += gridDim.x * blockDim.x) {
        float4 v = in[i];
        __half2 lo = __floats2half2_rn(v.x, v.y);
        __half2 hi = __floats2half2_rn(v.z, v.w);
        uint2 o;
        o.x = *(uint32_t*)&lo;
        o.y = *(uint32_t*)&hi;
        out[i] = o;
    }
}

// Router + fused fp16 conversion of x. One warp per token.
__global__ void router_kernel(const float* __restrict__ x, const float* __restrict__ gw) {
    extern __shared__ float s_gw[];  // NE*HD = 64 KB
    for (int i = threadIdx.x; i < NE * HD; i += blockDim.x) s_gw[i] = gw[i];
    __syncthreads();

    int gtid = blockIdx.x * blockDim.x + threadIdx.x;
    int t = gtid >> 5, lane = gtid & 31;
    if (t >= TOK) return;

    float acc[NE];
#pragma unroll
    for (int e = 0; e < NE; e++) acc[e] = 0.f;

    const float* xr = x + (size_t)t * HD;
    __half* xo = g_xh + (size_t)t * HD;
    for (int i = lane; i < HD; i += 32) {
        float xv = xr[i];
        xo[i] = __float2half_rn(xv);
#pragma unroll
        for (int e = 0; e < NE; e++) acc[e] += xv * s_gw[e * HD + i];
    }
#pragma unroll
    for (int e = 0; e < NE; e++) {
#pragma unroll
        for (int off = 16; off > 0; off >>= 1)
            acc[e] += __shfl_xor_sync(0xffffffffu, acc[e], off);
    }
    if (lane == 0) {
        int i0 = 0; float l0 = acc[0];
#pragma unroll
        for (int e = 1; e < NE; e++) if (acc[e] > l0) { l0 = acc[e]; i0 = e; }
        int i1 = -1; float l1 = -1e30f;
#pragma unroll
        for (int e = 0; e < NE; e++) if (e != i0 && acc[e] > l1) { l1 = acc[e]; i1 = e; }
        float ex = __expf(l1 - l0);
        float w0 = 1.f / (1.f + ex);
        float w1 = ex * w0;
        g_w2[2 * t] = w0;
        g_w2[2 * t + 1] = w1;
        int s0 = atomicAdd(&g_cnt[i0], 1);
        g_tokp[i0 * TOK + s0] = t;                          // k = 0
        int s1 = atomicAdd(&g_cnt[i1], 1);
        g_tokp[i1 * TOK + s1] = t | 0x80000000;             // k = 1
    }
}

// ---------------- GEMM1: h = silu(x@Wg)*(x@Wu); 192x128x64, 12 warps 64x32 ------
struct SmemG1 {
    __half A[3][BM][A_ST];     // 82944 B
    __half Bg[3][BK][B1_ST];   // 52224 B
    __half Bu[3][BK][B1_ST];   // 52224 B
    int    tok[BM];
};                             // ~184 KB -> 1 CTA/SM

__device__ __forceinline__ void g1_load(SmemG1* s, int st, int k0,
                                        const int* tok_s, int e, int n_base, int tid) {
#pragma unroll
    for (int i = 0; i < 4; i++) {                 // A: 192 rows x 8 chunks = 1536
        int idx = tid + i * NTHR;
        int row = idx >> 3, c = idx & 7;
        cp16(saddr(&s->A[st][row][c * 8]), &g_xh[(size_t)tok_s[row] * HD + k0 + c * 8]);
    }
    const __half* bg = g_wgh + ((size_t)e * HD + k0) * ID + n_base;
    const __half* bu = g_wuh + ((size_t)e * HD + k0) * ID + n_base;
    for (int idx = tid; idx < BK * 16; idx += NTHR) {   // 1024 chunks each
        int kr = idx >> 4, c = idx & 15;
        cp16(saddr(&s->Bg[st][kr][c * 8]), bg + (size_t)kr * ID + c * 8);
        cp16(saddr(&s->Bu[st][kr][c * 8]), bu + (size_t)kr * ID + c * 8);
    }
}

#define KT1 (HD / BK)   // 32

__global__ void __launch_bounds__(NTHR) gemm1_kernel() {
    extern __shared__ __align__(16) char smem_raw[];
    SmemG1* s = (SmemG1*)smem_raw;

    int e = blockIdx.z;
    int cnt = g_cnt[e];
    int m_base = blockIdx.y * BM;
    if (m_base >= cnt) return;
    int n_base = blockIdx.x * BN1;
    int tid = threadIdx.x;

    if (tid < BM) {
        int m = m_base + tid;
        s->tok[tid] = (m < cnt) ? (g_tokp[e * TOK + m] & 0x7fffffff) : 0;
    }
    __syncthreads();

    int wid = tid >> 5, lane = tid & 31;
    int wm = wid >> 2, wn = wid & 3;               // 3 x 4 warps, warp 64x32
    int r = lane >> 2, cq = lane & 3;
    int lrow = lane & 15, lcol = (lane >> 4) << 3;

    float acc_g[4][4][4], acc_u[4][4][4];
#pragma unroll
    for (int mf = 0; mf < 4; mf++)
#pragma unroll
        for (int nf = 0; nf < 4; nf++)
#pragma unroll
            for (int k = 0; k < 4; k++) { acc_g[mf][nf][k] = 0.f; acc_u[mf][nf][k] = 0.f; }

    g1_load(s, 0, 0, s->tok, e, n_base, tid);  cp_commit();
    g1_load(s, 1, BK, s->tok, e, n_base, tid); cp_commit();

    for (int kt = 0; kt < KT1; kt++) {
        cp_wait<1>();
        __syncthreads();
        int nxt = kt + 2;
        if (nxt < KT1) g1_load(s, nxt % 3, nxt * BK, s->tok, e, n_base, tid);
        cp_commit();

        int sg = kt % 3;
        uint32_t sA  = saddr(&s->A[sg][0][0]);
        uint32_t sBg = saddr(&s->Bg[sg][0][0]);
        uint32_t sBu = saddr(&s->Bu[sg][0][0]);
#pragma unroll
        for (int ks = 0; ks < BK / 16; ks++) {
            int k16 = ks * 16;
            uint32_t a[4][4];
#pragma unroll
            for (int mf = 0; mf < 4; mf++)
                ldsm_x4(a[mf], sA + 2 * ((wm * 64 + mf * 16 + lrow) * A_ST + k16 + lcol));
            uint32_t bg[2][4], bu[2][4];
#pragma unroll
            for (int ng = 0; ng < 2; ng++) {
                uint32_t off = 2 * ((k16 + lrow) * B1_ST + wn * 32 + ng * 16 + lcol);
                ldsm_x4t(bg[ng], sBg + off);
                ldsm_x4t(bu[ng], sBu + off);
            }
#pragma unroll
            for (int mf = 0; mf < 4; mf++)
#pragma unroll
                for (int nf = 0; nf < 4; nf++) {
                    mma_f16(acc_g[mf][nf], a[mf], &bg[nf >> 1][(nf & 1) * 2]);
                    mma_f16(acc_u[mf][nf], a[mf], &bu[nf >> 1][(nf & 1) * 2]);
                }
        }
    }

    // epilogue: silu(g)*u -> fp16 -> g_hh
#pragma unroll
    for (int mf = 0; mf < 4; mf++) {
#pragma unroll
        for (int nf = 0; nf < 4; nf++) {
            int rl = wm * 64 + mf * 16 + r;
            int col = n_base + wn * 32 + nf * 8 + cq * 2;
            if (m_base + rl < cnt) {
                float g0 = acc_g[mf][nf][0], u0 = acc_u[mf][nf][0];
                float g1 = acc_g[mf][nf][1], u1 = acc_u[mf][nf][1];
                float v0 = (g0 / (1.f + __expf(-g0))) * u0;
                float v1 = (g1 / (1.f + __expf(-g1))) * u1;
                __half2* p = (__half2*)&g_hh[((size_t)e * TOK + m_base + rl) * ID + col];
                *p = __floats2half2_rn(v0, v1);
            }
            if (m_base + rl + 8 < cnt) {
                float g0 = acc_g[mf][nf][2], u0 = acc_u[mf][nf][2];
                float g1 = acc_g[mf][nf][3], u1 = acc_u[mf][nf][3];
                float v0 = (g0 / (1.f + __expf(-g0))) * u0;
                float v1 = (g1 / (1.f + __expf(-g1))) * u1;
                __half2* p = (__half2*)&g_hh[((size_t)e * TOK + m_base + rl + 8) * ID + col];
                *p = __floats2half2_rn(v0, v1);
            }
        }
    }
}

// ---------------- GEMM2: y = h @ Wd; 192x256x64, 12 warps 64x64 -----------------
struct SmemG2 {
    __half A[3][BM][A_ST];     // 82944 B
    __half B[3][BK][B2_ST];    // 101376 B
    int    tokp[BM];
};                             // ~185 KB -> 1 CTA/SM

__device__ __forceinline__ void g2_load(SmemG2* s, int st, int k0,
                                        int e, int m_base, int n_base, int tid) {
    const __half* arow = g_hh + ((size_t)e * TOK + m_base) * ID + k0;
    const __half* brow = g_wdh + ((size_t)e * ID + k0) * HD + n_base;
#pragma unroll
    for (int i = 0; i < 4; i++) {                 // A: 1536 chunks
        int idx = tid + i * NTHR;
        int row = idx >> 3, c = idx & 7;
        cp16(saddr(&s->A[st][row][c * 8]), arow + (size_t)row * ID + c * 8);
    }
    for (int idx = tid; idx < BK * 32; idx += NTHR) {   // B: 2048 chunks
        int kr = idx >> 5, c = idx & 31;
        cp16(saddr(&s->B[st][kr][c * 8]), brow + (size_t)kr * HD + c * 8);
    }
}

#define KT2 (ID / BK)   // 22

__global__ void __launch_bounds__(NTHR) gemm2_kernel() {
    extern __shared__ __align__(16) char smem_raw[];
    SmemG2* s = (SmemG2*)smem_raw;

    int e = blockIdx.z;
    int cnt = g_cnt[e];
    int m_base = blockIdx.y * BM;
    if (m_base >= cnt) return;
    int n_base = blockIdx.x * BN2;
    int tid = threadIdx.x;

    if (tid < BM) {
        int m = m_base + tid;
        s->tokp[tid] = (m < cnt) ? g_tokp[e * TOK + m] : 0;
    }
    __syncthreads();

    int wid = tid >> 5, lane = tid & 31;
    int wm = wid >> 2, wn = wid & 3;               // 3 x 4 warps, warp 64x64
    int r = lane >> 2, cq = lane & 3;
    int lrow = lane & 15, lcol = (lane >> 4) << 3;

    float acc[4][8][4];
#pragma unroll
    for (int mf = 0; mf < 4; mf++)
#pragma unroll
        for (int nf = 0; nf < 8; nf++)
#pragma unroll
            for (int k = 0; k < 4; k++) acc[mf][nf][k] = 0.f;

    g2_load(s, 0, 0, e, m_base, n_base, tid);  cp_commit();
    g2_load(s, 1, BK, e, m_base, n_base, tid); cp_commit();

    for (int kt = 0; kt < KT2; kt++) {
        cp_wait<1>();
        __syncthreads();
        int nxt = kt + 2;
        if (nxt < KT2) g2_load(s, nxt % 3, nxt * BK, e, m_base, n_base, tid);
        cp_commit();

        int sg = kt % 3;
        uint32_t sA = saddr(&s->A[sg][0][0]);
        uint32_t sB = saddr(&s->B[sg][0][0]);
#pragma unroll
        for (int ks = 0; ks < BK / 16; ks++) {
            int k16 = ks * 16;
            uint32_t a[4][4];
#pragma unroll
            for (int mf = 0; mf < 4; mf++)
                ldsm_x4(a[mf], sA + 2 * ((wm * 64 + mf * 16 + lrow) * A_ST + k16 + lcol));
            uint32_t b[4][4];
#pragma unroll
            for (int ng = 0; ng < 4; ng++) {
                uint32_t off = 2 * ((k16 + lrow) * B2_ST + wn * 64 + ng * 16 + lcol);
                ldsm_x4t(b[ng], sB + off);
            }
#pragma unroll
            for (int mf = 0; mf < 4; mf++)
#pragma unroll
                for (int nf = 0; nf < 8; nf++)
                    mma_f16(acc[mf][nf], a[mf], &b[nf >> 1][(nf & 1) * 2]);
        }
    }

    // epilogue: plain stores to g_y[k][t]
#pragma unroll
    for (int mf = 0; mf < 4; mf++) {
#pragma unroll
        for (int nf = 0; nf < 8; nf++) {
            int rl = wm * 64 + mf * 16 + r;
            int col = n_base + wn * 64 + nf * 8 + cq * 2;
            if (m_base + rl < cnt) {
                int pk = s->tokp[rl];
                int t = pk & 0x7fffffff;
                int k = (uint32_t)pk >> 31;
                float2* p = (float2*)&g_y[((size_t)k * TOK + t) * HD + col];
                *p = make_float2(acc[mf][nf][0], acc[mf][nf][1]);
            }
            if (m_base + rl + 8 < cnt) {
                int pk = s->tokp[rl + 8];
                int t = pk & 0x7fffffff;
                int k = (uint32_t)pk >> 31;
                float2* p = (float2*)&g_y[((size_t)k * TOK + t) * HD + col];
                *p = make_float2(acc[mf][nf][2], acc[mf][nf][3]);
            }
        }
    }
}

// ---------------- combine: out = w0*y0 + w1*y1 ----------------------------------
__global__ void combine_kernel(float4* __restrict__ out) {
    const int n4 = TOK * HD / 4;
    const float4* y0 = (const float4*)g_y;
    const float4* y1 = y0 + n4;
    for (int i = blockIdx.x * blockDim.x + threadIdx.x; i < n4; i += gridDim.x * blockDim.x) {
        int t = i / (HD / 4);
        float w0 = g_w2[2 * t], w1 = g_w2[2 * t + 1];
        float4 a = y0[i], b = y1[i];
        float4 o;
        o.x = w0 * a.x + w1 * b.x;
        o.y = w0 * a.y + w1 * b.y;
        o.z = w0 * a.z + w1 * b.z;
        o.w = w0 * a.w + w1 * b.w;
        out[i] = o;
    }
}

// ---------------- host launcher -------------------------------------------------
extern "C" void kernel_launch(void* const* d_in, const int* in_sizes, int n_in,
                              void* d_out, int out_size) {
    const float* x  = (const float*)d_in[0];
    const float* gw = (const float*)d_in[1];
    const float* wg = (const float*)d_in[2];
    const float* wu = (const float*)d_in[3];
    const float* wd = (const float*)d_in[4];
    (void)in_sizes; (void)n_in; (void)out_size;

    zero_cnt_kernel<<<1, 32>>>();

    {
        dim3 grid(1024, 1, 3);
        conv_half_kernel<<<grid, 256>>>((const float4*)wg, (const float4*)wu,
                                        (const float4*)wd);
    }

    cudaFuncSetAttribute(router_kernel, cudaFuncAttributeMaxDynamicSharedMemorySize,
                         NE * HD * (int)sizeof(float));
    router_kernel<<<TOK * 32 / 256, 256, NE * HD * sizeof(float)>>>(x, gw);

    cudaFuncSetAttribute(gemm1_kernel, cudaFuncAttributeMaxDynamicSharedMemorySize,
                         (int)sizeof(SmemG1));
    dim3 grid1(ID / BN1, MBLK, NE);     // 11 x 43 x 8
    gemm1_kernel<<<grid1, NTHR, sizeof(SmemG1)>>>();

    cudaFuncSetAttribute(gemm2_kernel, cudaFuncAttributeMaxDynamicSharedMemorySize,
                         (int)sizeof(SmemG2));
    dim3 grid2(HD / BN2, MBLK, NE);     // 8 x 43 x 8
    gemm2_kernel<<<grid2, NTHR, sizeof(SmemG2)>>>();

    combine_kernel<<<2048, 256>>>((float4*)d_out);
}

// round 9
// speedup vs baseline: 2.2368x; 1.0641x over previous
#include <cuda_runtime.h>
#include <cuda_fp16.h>
#include <cstdint>

#define TOK 8192
#define HD  2048
#define ID  1408
#define NE  8

#define BM   128
#define BK   64
#define BN1  128
#define BN2  256
#define NTHR 384     // 256 consumer + 128 producer
#define NSTG 3
#define A_ST 72      // 64 + 8 halves -> 144B row stride
#define B1_ST 136    // 128 + 8 halves -> 272B
#define B2_ST 264    // 256 + 8 halves -> 528B

// ---------------- device scratch (no allocations allowed) ----------------------
__device__ __half g_xh[(size_t)TOK * HD];       // fp16 x
__device__ __half g_wgh[(size_t)NE * HD * ID];  // fp16 weights, native [k][n]
__device__ __half g_wuh[(size_t)NE * HD * ID];
__device__ __half g_wdh[(size_t)NE * ID * HD];
__device__ int    g_cnt[NE];
__device__ int    g_tokp[NE * TOK];             // token | (k<<31)
__device__ float  g_w2[TOK * 2];                // per-token (w0, w1)
__device__ __half g_hh[(size_t)NE * TOK * ID];  // fp16 intermediate (slot-indexed)
__device__ float  g_y[(size_t)2 * TOK * HD];    // unweighted expert outputs per k

// ---------------- helpers ------------------------------------------------------
__device__ __forceinline__ uint32_t saddr(const void* p) {
    return (uint32_t)__cvta_generic_to_shared(p);
}
__device__ __forceinline__ void cp16(uint32_t dst, const void* src) {
    asm volatile("cp.async.cg.shared.global [%0], [%1], 16;" :: "r"(dst), "l"(src));
}
__device__ __forceinline__ void cp_commit() { asm volatile("cp.async.commit_group;"); }
template <int N>
__device__ __forceinline__ void cp_wait() { asm volatile("cp.async.wait_group %0;" :: "n"(N)); }

__device__ __forceinline__ void bar_sync(int id) {
    asm volatile("bar.sync %0, %1;" :: "r"(id), "n"(NTHR) : "memory");
}
__device__ __forceinline__ void bar_arrive(int id) {
    asm volatile("bar.arrive %0, %1;" :: "r"(id), "n"(NTHR) : "memory");
}

__device__ __forceinline__ void ldsm_x4(uint32_t* r, uint32_t addr) {
    asm volatile("ldmatrix.sync.aligned.m8n8.x4.shared.b16 {%0,%1,%2,%3}, [%4];"
                 : "=r"(r[0]), "=r"(r[1]), "=r"(r[2]), "=r"(r[3]) : "r"(addr));
}
__device__ __forceinline__ void ldsm_x4t(uint32_t* r, uint32_t addr) {
    asm volatile("ldmatrix.sync.aligned.m8n8.x4.trans.shared.b16 {%0,%1,%2,%3}, [%4];"
                 : "=r"(r[0]), "=r"(r[1]), "=r"(r[2]), "=r"(r[3]) : "r"(addr));
}
__device__ __forceinline__ void mma_f16(float d[4], const uint32_t a[4], const uint32_t b[2]) {
    asm volatile(
        "mma.sync.aligned.m16n8k16.row.col.f32.f16.f16.f32 "
        "{%0,%1,%2,%3}, {%4,%5,%6,%7}, {%8,%9}, {%0,%1,%2,%3};"
        : "+f"(d[0]), "+f"(d[1]), "+f"(d[2]), "+f"(d[3])
        : "r"(a[0]), "r"(a[1]), "r"(a[2]), "r"(a[3]), "r"(b[0]), "r"(b[1]));
}

// ---------------- small kernels ------------------------------------------------
__global__ void zero_cnt_kernel() {
    if (threadIdx.x < NE) g_cnt[threadIdx.x] = 0;
}

__global__ void conv_half_kernel(const float4* __restrict__ wg,
                                 const float4* __restrict__ wu,
                                 const float4* __restrict__ wd) {
    const int n4 = NE * HD * ID / 4;
    const float4* in = blockIdx.z == 0 ? wg : blockIdx.z == 1 ? wu : wd;
    uint2* out = (uint2*)(blockIdx.z == 0 ? g_wgh : blockIdx.z == 1 ? g_wuh : g_wdh);
    for (int i = blockIdx.x * blockDim.x + threadIdx.x; i < n4; i += gridDim.x * blockDim.x) {
        float4 v = in[i];
        __half2 lo = __floats2half2_rn(v.x, v.y);
        __half2 hi = __floats2half2_rn(v.z, v.w);
        uint2 o;
        o.x = *(uint32_t*)&lo;
        o.y = *(uint32_t*)&hi;
        out[i] = o;
    }
}

// Router + fused fp16 conversion of x. One warp per token.
__global__ void router_kernel(const float* __restrict__ x, const float* __restrict__ gw) {
    extern __shared__ float s_gw[];  // NE*HD = 64 KB
    for (int i = threadIdx.x; i < NE * HD; i += blockDim.x) s_gw[i] = gw[i];
    __syncthreads();

    int gtid = blockIdx.x * blockDim.x + threadIdx.x;
    int t = gtid >> 5, lane = gtid & 31;
    if (t >= TOK) return;

    float acc[NE];
#pragma unroll
    for (int e = 0; e < NE; e++) acc[e] = 0.f;

    const float* xr = x + (size_t)t * HD;
    __half* xo = g_xh + (size_t)t * HD;
    for (int i = lane; i < HD; i += 32) {
        float xv = xr[i];
        xo[i] = __float2half_rn(xv);
#pragma unroll
        for (int e = 0; e < NE; e++) acc[e] += xv * s_gw[e * HD + i];
    }
#pragma unroll
    for (int e = 0; e < NE; e++) {
#pragma unroll
        for (int off = 16; off > 0; off >>= 1)
            acc[e] += __shfl_xor_sync(0xffffffffu, acc[e], off);
    }
    if (lane == 0) {
        int i0 = 0; float l0 = acc[0];
#pragma unroll
        for (int e = 1; e < NE; e++) if (acc[e] > l0) { l0 = acc[e]; i0 = e; }
        int i1 = -1; float l1 = -1e30f;
#pragma unroll
        for (int e = 0; e < NE; e++) if (e != i0 && acc[e] > l1) { l1 = acc[e]; i1 = e; }
        float ex = __expf(l1 - l0);
        float w0 = 1.f / (1.f + ex);
        float w1 = ex * w0;
        g_w2[2 * t] = w0;
        g_w2[2 * t + 1] = w1;
        int s0 = atomicAdd(&g_cnt[i0], 1);
        g_tokp[i0 * TOK + s0] = t;                          // k = 0
        int s1 = atomicAdd(&g_cnt[i1], 1);
        g_tokp[i1 * TOK + s1] = t | 0x80000000;             // k = 1
    }
}

// ---------------- GEMM1: h = silu(x@Wg)*(x@Wu); warp-specialized ----------------
// 8 consumer warps (2x4, warp 64x32 for both g and u) + 4 producer warps.
struct SmemG1 {
    __half A[NSTG][BM][A_ST];     // 55296 B
    __half Bg[NSTG][BK][B1_ST];   // 52224 B
    __half Bu[NSTG][BK][B1_ST];   // 52224 B
    int    tok[BM];
};                                // ~160 KB

__device__ __forceinline__ void g1_load(SmemG1* s, int st, int k0,
                                        const int* tok_s, int e, int n_base, int ptid) {
#pragma unroll
    for (int i = 0; i < 8; i++) {                 // A: 128x8 = 1024 chunks
        int idx = ptid + i * 128;
        int row = idx >> 3, c = idx & 7;
        cp16(saddr(&s->A[st][row][c * 8]), &g_xh[(size_t)tok_s[row] * HD + k0 + c * 8]);
    }
    const __half* bg = g_wgh + ((size_t)e * HD + k0) * ID + n_base;
    const __half* bu = g_wuh + ((size_t)e * HD + k0) * ID + n_base;
#pragma unroll
    for (int i = 0; i < 8; i++) {                 // Bg/Bu: 64x16 = 1024 chunks each
        int idx = ptid + i * 128;
        int kr = idx >> 4, c = idx & 15;
        cp16(saddr(&s->Bg[st][kr][c * 8]), bg + (size_t)kr * ID + c * 8);
        cp16(saddr(&s->Bu[st][kr][c * 8]), bu + (size_t)kr * ID + c * 8);
    }
}

#define KT1 (HD / BK)   // 32

__global__ void __launch_bounds__(NTHR) gemm1_kernel() {
    extern __shared__ __align__(16) char smem_raw[];
    SmemG1* s = (SmemG1*)smem_raw;

    int e = blockIdx.z;
    int cnt = g_cnt[e];
    int m_base = blockIdx.y * BM;
    if (m_base >= cnt) return;
    int n_base = blockIdx.x * BN1;
    int tid = threadIdx.x;

    if (tid < BM) {
        int m = m_base + tid;
        s->tok[tid] = (m < cnt) ? (g_tokp[e * TOK + m] & 0x7fffffff) : 0;
    }
    __syncthreads();

    if (tid >= 256) {
        // ---------------- producer (4 warps) ----------------
        int ptid = tid - 256;
        for (int kt = 0; kt < KT1; kt++) {
            int sg = kt % NSTG;
            if (kt >= NSTG) bar_sync(4 + sg);                 // EMPTY
            g1_load(s, sg, kt * BK, s->tok, e, n_base, ptid);
            cp_commit();
            if (kt >= 1) { cp_wait<1>(); bar_arrive(1 + (kt - 1) % NSTG); }  // FULL
        }
        cp_wait<0>();
        bar_arrive(1 + (KT1 - 1) % NSTG);
        return;
    }

    // ---------------- consumer (8 warps) ----------------
    int wid = tid >> 5, lane = tid & 31;
    int wm = wid >> 2, wn = wid & 3;               // 2 x 4 warps, warp 64x32
    int r = lane >> 2, cq = lane & 3;
    int lrow = lane & 15, lcol = (lane >> 4) << 3;

    float acc_g[4][4][4], acc_u[4][4][4];
#pragma unroll
    for (int mf = 0; mf < 4; mf++)
#pragma unroll
        for (int nf = 0; nf < 4; nf++)
#pragma unroll
            for (int k = 0; k < 4; k++) { acc_g[mf][nf][k] = 0.f; acc_u[mf][nf][k] = 0.f; }

    for (int kt = 0; kt < KT1; kt++) {
        int sg = kt % NSTG;
        bar_sync(1 + sg);                                     // FULL
        uint32_t sA  = saddr(&s->A[sg][0][0]);
        uint32_t sBg = saddr(&s->Bg[sg][0][0]);
        uint32_t sBu = saddr(&s->Bu[sg][0][0]);
#pragma unroll
        for (int ks = 0; ks < BK / 16; ks++) {
            int k16 = ks * 16;
            uint32_t a[4][4];
#pragma unroll
            for (int mf = 0; mf < 4; mf++)
                ldsm_x4(a[mf], sA + 2 * ((wm * 64 + mf * 16 + lrow) * A_ST + k16 + lcol));
            uint32_t bg[2][4], bu[2][4];
#pragma unroll
            for (int ng = 0; ng < 2; ng++) {
                uint32_t off = 2 * ((k16 + lrow) * B1_ST + wn * 32 + ng * 16 + lcol);
                ldsm_x4t(bg[ng], sBg + off);
                ldsm_x4t(bu[ng], sBu + off);
            }
#pragma unroll
            for (int mf = 0; mf < 4; mf++)
#pragma unroll
                for (int nf = 0; nf < 4; nf++) {
                    mma_f16(acc_g[mf][nf], a[mf], &bg[nf >> 1][(nf & 1) * 2]);
                    mma_f16(acc_u[mf][nf], a[mf], &bu[nf >> 1][(nf & 1) * 2]);
                }
        }
        bar_arrive(4 + sg);                                   // EMPTY
    }

    // epilogue: silu(g)*u -> fp16 -> g_hh
#pragma unroll
    for (int mf = 0; mf < 4; mf++) {
#pragma unroll
        for (int nf = 0; nf < 4; nf++) {
            int rl = wm * 64 + mf * 16 + r;
            int col = n_base + wn * 32 + nf * 8 + cq * 2;
            if (m_base + rl < cnt) {
                float g0 = acc_g[mf][nf][0], u0 = acc_u[mf][nf][0];
                float g1 = acc_g[mf][nf][1], u1 = acc_u[mf][nf][1];
                float v0 = (g0 / (1.f + __expf(-g0))) * u0;
                float v1 = (g1 / (1.f + __expf(-g1))) * u1;
                __half2* p = (__half2*)&g_hh[((size_t)e * TOK + m_base + rl) * ID + col];
                *p = __floats2half2_rn(v0, v1);
            }
            if (m_base + rl + 8 < cnt) {
                float g0 = acc_g[mf][nf][2], u0 = acc_u[mf][nf][2];
                float g1 = acc_g[mf][nf][3], u1 = acc_u[mf][nf][3];
                float v0 = (g0 / (1.f + __expf(-g0))) * u0;
                float v1 = (g1 / (1.f + __expf(-g1))) * u1;
                __half2* p = (__half2*)&g_hh[((size_t)e * TOK + m_base + rl + 8) * ID + col];
                *p = __floats2half2_rn(v0, v1);
            }
        }
    }
}

// ---------------- GEMM2: y = h @ Wd; warp-specialized ---------------------------
// 8 consumer warps (2x4, warp 64x64) + 4 producer warps.
struct SmemG2 {
    __half A[NSTG][BM][A_ST];     // 55296 B
    __half B[NSTG][BK][B2_ST];    // 101376 B
    int    tokp[BM];
};                                // ~157 KB

__device__ __forceinline__ void g2_load(SmemG2* s, int st, int k0,
                                        int e, int m_base, int n_base, int ptid) {
    const __half* arow = g_hh + ((size_t)e * TOK + m_base) * ID + k0;
    const __half* brow = g_wdh + ((size_t)e * ID + k0) * HD + n_base;
#pragma unroll
    for (int i = 0; i < 8; i++) {                 // A: 1024 chunks
        int idx = ptid + i * 128;
        int row = idx >> 3, c = idx & 7;
        cp16(saddr(&s->A[st][row][c * 8]), arow + (size_t)row * ID + c * 8);
    }
#pragma unroll
    for (int i = 0; i < 16; i++) {                // B: 64x32 = 2048 chunks
        int idx = ptid + i * 128;
        int kr = idx >> 5, c = idx & 31;
        cp16(saddr(&s->B[st][kr][c * 8]), brow + (size_t)kr * HD + c * 8);
    }
}

#define KT2 (ID / BK)   // 22

__global__ void __launch_bounds__(NTHR) gemm2_kernel() {
    extern __shared__ __align__(16) char smem_raw[];
    SmemG2* s = (SmemG2*)smem_raw;

    int e = blockIdx.z;
    int cnt = g_cnt[e];
    int m_base = blockIdx.y * BM;
    if (m_base >= cnt) return;
    int n_base = blockIdx.x * BN2;
    int tid = threadIdx.x;

    if (tid < BM) {
        int m = m_base + tid;
        s->tokp[tid] = (m < cnt) ? g_tokp[e * TOK + m] : 0;
    }
    __syncthreads();

    if (tid >= 256) {
        // ---------------- producer (4 warps) ----------------
        int ptid = tid - 256;
        for (int kt = 0; kt < KT2; kt++) {
            int sg = kt % NSTG;
            if (kt >= NSTG) bar_sync(4 + sg);                 // EMPTY
            g2_load(s, sg, kt * BK, e, m_base, n_base, ptid);
            cp_commit();
            if (kt >= 1) { cp_wait<1>(); bar_arrive(1 + (kt - 1) % NSTG); }  // FULL
        }
        cp_wait<0>();
        bar_arrive(1 + (KT2 - 1) % NSTG);
        return;
    }

    // ---------------- consumer (8 warps) ----------------
    int wid = tid >> 5, lane = tid & 31;
    int wm = wid >> 2, wn = wid & 3;               // 2 x 4 warps, warp 64x64
    int r = lane >> 2, cq = lane & 3;
    int lrow = lane & 15, lcol = (lane >> 4) << 3;

    float acc[4][8][4];
#pragma unroll
    for (int mf = 0; mf < 4; mf++)
#pragma unroll
        for (int nf = 0; nf < 8; nf++)
#pragma unroll
            for (int k = 0; k < 4; k++) acc[mf][nf][k] = 0.f;

    for (int kt = 0; kt < KT2; kt++) {
        int sg = kt % NSTG;
        bar_sync(1 + sg);                                     // FULL
        uint32_t sA = saddr(&s->A[sg][0][0]);
        uint32_t sB = saddr(&s->B[sg][0][0]);
#pragma unroll
        for (int ks = 0; ks < BK / 16; ks++) {
            int k16 = ks * 16;
            uint32_t a[4][4];
#pragma unroll
            for (int mf = 0; mf < 4; mf++)
                ldsm_x4(a[mf], sA + 2 * ((wm * 64 + mf * 16 + lrow) * A_ST + k16 + lcol));
            uint32_t b[4][4];
#pragma unroll
            for (int ng = 0; ng < 4; ng++) {
                uint32_t off = 2 * ((k16 + lrow) * B2_ST + wn * 64 + ng * 16 + lcol);
                ldsm_x4t(b[ng], sB + off);
            }
#pragma unroll
            for (int mf = 0; mf < 4; mf++)
#pragma unroll
                for (int nf = 0; nf < 8; nf++)
                    mma_f16(acc[mf][nf], a[mf], &b[nf >> 1][(nf & 1) * 2]);
        }
        bar_arrive(4 + sg);                                   // EMPTY
    }

    // epilogue: plain stores to g_y[k][t]
#pragma unroll
    for (int mf = 0; mf < 4; mf++) {
#pragma unroll
        for (int nf = 0; nf < 8; nf++) {
            int rl = wm * 64 + mf * 16 + r;
            int col = n_base + wn * 64 + nf * 8 + cq * 2;
            if (m_base + rl < cnt) {
                int pk = s->tokp[rl];
                int t = pk & 0x7fffffff;
                int k = (uint32_t)pk >> 31;
                float2* p = (float2*)&g_y[((size_t)k * TOK + t) * HD + col];
                *p = make_float2(acc[mf][nf][0], acc[mf][nf][1]);
            }
            if (m_base + rl + 8 < cnt) {
                int pk = s->tokp[rl + 8];
                int t = pk & 0x7fffffff;
                int k = (uint32_t)pk >> 31;
                float2* p = (float2*)&g_y[((size_t)k * TOK + t) * HD + col];
                *p = make_float2(acc[mf][nf][2], acc[mf][nf][3]);
            }
        }
    }
}

// ---------------- combine: out = w0*y0 + w1*y1 ----------------------------------
__global__ void combine_kernel(float4* __restrict__ out) {
    const int n4 = TOK * HD / 4;
    const float4* y0 = (const float4*)g_y;
    const float4* y1 = y0 + n4;
    for (int i = blockIdx.x * blockDim.x + threadIdx.x; i < n4; i += gridDim.x * blockDim.x) {
        int t = i / (HD / 4);
        float w0 = g_w2[2 * t], w1 = g_w2[2 * t + 1];
        float4 a = y0[i], b = y1[i];
        float4 o;
        o.x = w0 * a.x + w1 * b.x;
        o.y = w0 * a.y + w1 * b.y;
        o.z = w0 * a.z + w1 * b.z;
        o.w = w0 * a.w + w1 * b.w;
        out[i] = o;
    }
}

// ---------------- host launcher -------------------------------------------------
extern "C" void kernel_launch(void* const* d_in, const int* in_sizes, int n_in,
                              void* d_out, int out_size) {
    const float* x  = (const float*)d_in[0];
    const float* gw = (const float*)d_in[1];
    const float* wg = (const float*)d_in[2];
    const float* wu = (const float*)d_in[3];
    const float* wd = (const float*)d_in[4];
    (void)in_sizes; (void)n_in; (void)out_size;

    zero_cnt_kernel<<<1, 32>>>();

    {
        dim3 grid(1024, 1, 3);
        conv_half_kernel<<<grid, 256>>>((const float4*)wg, (const float4*)wu,
                                        (const float4*)wd);
    }

    cudaFuncSetAttribute(router_kernel, cudaFuncAttributeMaxDynamicSharedMemorySize,
                         NE * HD * (int)sizeof(float));
    router_kernel<<<TOK * 32 / 256, 256, NE * HD * sizeof(float)>>>(x, gw);

    cudaFuncSetAttribute(gemm1_kernel, cudaFuncAttributeMaxDynamicSharedMemorySize,
                         (int)sizeof(SmemG1));
    dim3 grid1(ID / BN1, TOK / BM, NE);     // 11 x 64 x 8
    gemm1_kernel<<<grid1, NTHR, sizeof(SmemG1)>>>();

    cudaFuncSetAttribute(gemm2_kernel, cudaFuncAttributeMaxDynamicSharedMemorySize,
                         (int)sizeof(SmemG2));
    dim3 grid2(HD / BN2, TOK / BM, NE);     // 8 x 64 x 8
    gemm2_kernel<<<grid2, NTHR, sizeof(SmemG2)>>>();

    combine_kernel<<<2048, 256>>>((float4*)d_out);
}

// round 10
// speedup vs baseline: 2.2418x; 1.0022x over previous
#include <cuda_runtime.h>
#include <cuda_fp16.h>
#include <cstdint>

#define TOK 8192
#define HD  2048
#define ID  1408
#define NE  8

#define BM   128
#define BK   64
#define BN1  128
#define BN2  256
#define NT1  (ID / BN1)   // 11
#define NT2  (HD / BN2)   // 8
#define NTHR 384          // 256 consumer + 128 producer
#define NSTG 4
#define KT1  (HD / BK)    // 32
#define KT2  (ID / BK)    // 22
#define A_ST 72           // 64 + 8 halves -> 144B row stride
#define B1_ST 136         // 128 + 8 halves -> 272B
#define B2_ST 264         // 256 + 8 halves -> 528B

// ---------------- device scratch (no allocations allowed) ----------------------
__device__ __half g_xh[(size_t)TOK * HD];       // fp16 x
__device__ __half g_wgh[(size_t)NE * HD * ID];  // fp16 weights, native [k][n]
__device__ __half g_wuh[(size_t)NE * HD * ID];
__device__ __half g_wdh[(size_t)NE * ID * HD];
__device__ int    g_cnt[NE];
__device__ int    g_tokp[NE * TOK];             // token | (k<<31)
__device__ float  g_w2[TOK * 2];                // per-token (w0, w1)
__device__ __half g_hh[(size_t)NE * TOK * ID];  // fp16 intermediate (slot-indexed)
__device__ float  g_y[(size_t)2 * TOK * HD];    // unweighted expert outputs per k

// ---------------- helpers ------------------------------------------------------
__device__ __forceinline__ uint32_t saddr(const void* p) {
    return (uint32_t)__cvta_generic_to_shared(p);
}
__device__ __forceinline__ void cp16(uint32_t dst, const void* src) {
    asm volatile("cp.async.cg.shared.global [%0], [%1], 16;" :: "r"(dst), "l"(src));
}
__device__ __forceinline__ void cp_commit() { asm volatile("cp.async.commit_group;"); }
template <int N>
__device__ __forceinline__ void cp_wait() { asm volatile("cp.async.wait_group %0;" :: "n"(N)); }

__device__ __forceinline__ void bar_sync(int id) {
    asm volatile("bar.sync %0, %1;" :: "r"(id), "n"(NTHR) : "memory");
}
__device__ __forceinline__ void bar_arrive(int id) {
    asm volatile("bar.arrive %0, %1;" :: "r"(id), "n"(NTHR) : "memory");
}

__device__ __forceinline__ void ldsm_x4(uint32_t* r, uint32_t addr) {
    asm volatile("ldmatrix.sync.aligned.m8n8.x4.shared.b16 {%0,%1,%2,%3}, [%4];"
                 : "=r"(r[0]), "=r"(r[1]), "=r"(r[2]), "=r"(r[3]) : "r"(addr));
}
__device__ __forceinline__ void ldsm_x4t(uint32_t* r, uint32_t addr) {
    asm volatile("ldmatrix.sync.aligned.m8n8.x4.trans.shared.b16 {%0,%1,%2,%3}, [%4];"
                 : "=r"(r[0]), "=r"(r[1]), "=r"(r[2]), "=r"(r[3]) : "r"(addr));
}
__device__ __forceinline__ void mma_f16(float d[4], const uint32_t a[4], const uint32_t b[2]) {
    asm volatile(
        "mma.sync.aligned.m16n8k16.row.col.f32.f16.f16.f32 "
        "{%0,%1,%2,%3}, {%4,%5,%6,%7}, {%8,%9}, {%0,%1,%2,%3};"
        : "+f"(d[0]), "+f"(d[1]), "+f"(d[2]), "+f"(d[3])
        : "r"(a[0]), "r"(a[1]), "r"(a[2]), "r"(a[3]), "r"(b[0]), "r"(b[1]));
}

// ---------------- tile scheduler -------------------------------------------------
__device__ __forceinline__ int total_tiles(int NT) {
    int T = 0;
#pragma unroll
    for (int ee = 0; ee < NE; ee++) T += ((g_cnt[ee] + BM - 1) / BM) * NT;
    return T;
}
// decode flat tile -> (e, m_base, n_idx, cnt); m-index inner so consecutive tiles
// share the same weight n-slice in L2.
__device__ __forceinline__ void decode_tile(int tile, int NT, int& e_o, int& mb_o,
                                            int& nb_idx_o, int& cnt_o) {
    int rem = tile, e = -1, mt_e = 1, cnt_e = 0;
#pragma unroll
    for (int ee = 0; ee < NE; ee++) {
        int c = g_cnt[ee];
        int mt = (c + BM - 1) / BM;
        int te = mt * NT;
        if (e < 0) {
            if (rem < te) { e = ee; mt_e = mt; cnt_e = c; }
            else rem -= te;
        }
    }
    e_o = e;
    cnt_o = cnt_e;
    mb_o = (rem % mt_e) * BM;
    nb_idx_o = rem / mt_e;
}

// ---------------- small kernels ------------------------------------------------
__global__ void zero_cnt_kernel() {
    if (threadIdx.x < NE) g_cnt[threadIdx.x] = 0;
}

__global__ void conv_half_kernel(const float4* __restrict__ wg,
                                 const float4* __restrict__ wu,
                                 const float4* __restrict__ wd) {
    const int n4 = NE * HD * ID / 4;
    const float4* in = blockIdx.z == 0 ? wg : blockIdx.z == 1 ? wu : wd;
    uint2* out = (uint2*)(blockIdx.z == 0 ? g_wgh : blockIdx.z == 1 ? g_wuh : g_wdh);
    for (int i = blockIdx.x * blockDim.x + threadIdx.x; i < n4; i += gridDim.x * blockDim.x) {
        float4 v = in[i];
        __half2 lo = __floats2half2_rn(v.x, v.y);
        __half2 hi = __floats2half2_rn(v.z, v.w);
        uint2 o;
        o.x = *(uint32_t*)&lo;
        o.y = *(uint32_t*)&hi;
        out[i] = o;
    }
}

// Router + fused fp16 conversion of x. One warp per token.
__global__ void router_kernel(const float* __restrict__ x, const float* __restrict__ gw) {
    extern __shared__ float s_gw[];  // NE*HD = 64 KB
    for (int i = threadIdx.x; i < NE * HD; i += blockDim.x) s_gw[i] = gw[i];
    __syncthreads();

    int gtid = blockIdx.x * blockDim.x + threadIdx.x;
    int t = gtid >> 5, lane = gtid & 31;
    if (t >= TOK) return;

    float acc[NE];
#pragma unroll
    for (int e = 0; e < NE; e++) acc[e] = 0.f;

    const float* xr = x + (size_t)t * HD;
    __half* xo = g_xh + (size_t)t * HD;
    for (int i = lane; i < HD; i += 32) {
        float xv = xr[i];
        xo[i] = __float2half_rn(xv);
#pragma unroll
        for (int e = 0; e < NE; e++) acc[e] += xv * s_gw[e * HD + i];
    }
#pragma unroll
    for (int e = 0; e < NE; e++) {
#pragma unroll
        for (int off = 16; off > 0; off >>= 1)
            acc[e] += __shfl_xor_sync(0xffffffffu, acc[e], off);
    }
    if (lane == 0) {
        int i0 = 0; float l0 = acc[0];
#pragma unroll
        for (int e = 1; e < NE; e++) if (acc[e] > l0) { l0 = acc[e]; i0 = e; }
        int i1 = -1; float l1 = -1e30f;
#pragma unroll
        for (int e = 0; e < NE; e++) if (e != i0 && acc[e] > l1) { l1 = acc[e]; i1 = e; }
        float ex = __expf(l1 - l0);
        float w0 = 1.f / (1.f + ex);
        float w1 = ex * w0;
        g_w2[2 * t] = w0;
        g_w2[2 * t + 1] = w1;
        int s0 = atomicAdd(&g_cnt[i0], 1);
        g_tokp[i0 * TOK + s0] = t;                          // k = 0
        int s1 = atomicAdd(&g_cnt[i1], 1);
        g_tokp[i1 * TOK + s1] = t | 0x80000000;             // k = 1
    }
}

// ---------------- GEMM1: persistent warp-specialized ----------------------------
struct SmemG1 {
    __half A[NSTG][BM][A_ST];     // 73728 B
    __half Bg[NSTG][BK][B1_ST];   // 69632 B
    __half Bu[NSTG][BK][B1_ST];   // 69632 B
};                                // 212992 B

__device__ __forceinline__ void g1_load(SmemG1* s, int st, int k0, const int* tok8,
                                        int e, int n_base, int ptid) {
#pragma unroll
    for (int i = 0; i < 8; i++) {                 // A: 128x8 = 1024 chunks
        int idx = ptid + i * 128;
        int row = idx >> 3, c = idx & 7;
        cp16(saddr(&s->A[st][row][c * 8]), &g_xh[(size_t)tok8[i] * HD + k0 + c * 8]);
    }
    const __half* bg = g_wgh + ((size_t)e * HD + k0) * ID + n_base;
    const __half* bu = g_wuh + ((size_t)e * HD + k0) * ID + n_base;
#pragma unroll
    for (int i = 0; i < 8; i++) {                 // Bg/Bu: 64x16 = 1024 chunks each
        int idx = ptid + i * 128;
        int kr = idx >> 4, c = idx & 15;
        cp16(saddr(&s->Bg[st][kr][c * 8]), bg + (size_t)kr * ID + c * 8);
        cp16(saddr(&s->Bu[st][kr][c * 8]), bu + (size_t)kr * ID + c * 8);
    }
}

__global__ void __launch_bounds__(NTHR) gemm1_kernel() {
    extern __shared__ __align__(16) char smem_raw[];
    SmemG1* s = (SmemG1*)smem_raw;
    int tid = threadIdx.x;
    const int T = total_tiles(NT1);

    if (tid >= 256) {
        // ---------------- producer (4 warps) ----------------
        int ptid = tid - 256;
        int base_row = ptid >> 3;
        int g = 0;
        for (int tile = blockIdx.x; tile < T; tile += gridDim.x) {
            int e, m_base, n_idx, cnt;
            decode_tile(tile, NT1, e, m_base, n_idx, cnt);
            int n_base = n_idx * BN1;
            int tok8[8];
#pragma unroll
            for (int i = 0; i < 8; i++) {
                int m = m_base + base_row + 16 * i;
                tok8[i] = (m < cnt) ? (g_tokp[e * TOK + m] & 0x7fffffff) : 0;
            }
            for (int kt = 0; kt < KT1; kt++) {
                int sg = g & 3;
                if (g >= NSTG) bar_sync(5 + sg);               // EMPTY
                g1_load(s, sg, kt * BK, tok8, e, n_base, ptid);
                cp_commit();
                if (g >= 1) { cp_wait<1>(); bar_arrive(1 + ((g - 1) & 3)); }  // FULL
                g++;
            }
        }
        if (g >= 1) { cp_wait<0>(); bar_arrive(1 + ((g - 1) & 3)); }
        return;
    }

    // ---------------- consumer (8 warps) ----------------
    int wid = tid >> 5, lane = tid & 31;
    int wm = wid >> 2, wn = wid & 3;               // 2 x 4 warps, warp 64x32
    int r = lane >> 2, cq = lane & 3;
    int lrow = lane & 15, lcol = (lane >> 4) << 3;
    int g = 0;

    for (int tile = blockIdx.x; tile < T; tile += gridDim.x) {
        int e, m_base, n_idx, cnt;
        decode_tile(tile, NT1, e, m_base, n_idx, cnt);
        int n_base = n_idx * BN1;

        float acc_g[4][4][4], acc_u[4][4][4];
#pragma unroll
        for (int mf = 0; mf < 4; mf++)
#pragma unroll
            for (int nf = 0; nf < 4; nf++)
#pragma unroll
                for (int k = 0; k < 4; k++) { acc_g[mf][nf][k] = 0.f; acc_u[mf][nf][k] = 0.f; }

        for (int kt = 0; kt < KT1; kt++) {
            int sg = g & 3;
            bar_sync(1 + sg);                                 // FULL
            uint32_t sA  = saddr(&s->A[sg][0][0]);
            uint32_t sBg = saddr(&s->Bg[sg][0][0]);
            uint32_t sBu = saddr(&s->Bu[sg][0][0]);
#pragma unroll
            for (int ks = 0; ks < BK / 16; ks++) {
                int k16 = ks * 16;
                uint32_t a[4][4];
#pragma unroll
                for (int mf = 0; mf < 4; mf++)
                    ldsm_x4(a[mf], sA + 2 * ((wm * 64 + mf * 16 + lrow) * A_ST + k16 + lcol));
                uint32_t bg[2][4], bu[2][4];
#pragma unroll
                for (int ng = 0; ng < 2; ng++) {
                    uint32_t off = 2 * ((k16 + lrow) * B1_ST + wn * 32 + ng * 16 + lcol);
                    ldsm_x4t(bg[ng], sBg + off);
                    ldsm_x4t(bu[ng], sBu + off);
                }
#pragma unroll
                for (int mf = 0; mf < 4; mf++)
#pragma unroll
                    for (int nf = 0; nf < 4; nf++) {
                        mma_f16(acc_g[mf][nf], a[mf], &bg[nf >> 1][(nf & 1) * 2]);
                        mma_f16(acc_u[mf][nf], a[mf], &bu[nf >> 1][(nf & 1) * 2]);
                    }
            }
            bar_arrive(5 + sg);                               // EMPTY
            g++;
        }

        // epilogue: silu(g)*u -> fp16 -> g_hh (overlaps producer's next-tile loads)
#pragma unroll
        for (int mf = 0; mf < 4; mf++) {
#pragma unroll
            for (int nf = 0; nf < 4; nf++) {
                int rl = wm * 64 + mf * 16 + r;
                int col = n_base + wn * 32 + nf * 8 + cq * 2;
                if (m_base + rl < cnt) {
                    float g0 = acc_g[mf][nf][0], u0 = acc_u[mf][nf][0];
                    float g1 = acc_g[mf][nf][1], u1 = acc_u[mf][nf][1];
                    float v0 = (g0 / (1.f + __expf(-g0))) * u0;
                    float v1 = (g1 / (1.f + __expf(-g1))) * u1;
                    __half2* p = (__half2*)&g_hh[((size_t)e * TOK + m_base + rl) * ID + col];
                    *p = __floats2half2_rn(v0, v1);
                }
                if (m_base + rl + 8 < cnt) {
                    float g0 = acc_g[mf][nf][2], u0 = acc_u[mf][nf][2];
                    float g1 = acc_g[mf][nf][3], u1 = acc_u[mf][nf][3];
                    float v0 = (g0 / (1.f + __expf(-g0))) * u0;
                    float v1 = (g1 / (1.f + __expf(-g1))) * u1;
                    __half2* p = (__half2*)&g_hh[((size_t)e * TOK + m_base + rl + 8) * ID + col];
                    *p = __floats2half2_rn(v0, v1);
                }
            }
        }
    }
}

// ---------------- GEMM2: persistent warp-specialized ----------------------------
struct SmemG2 {
    __half A[NSTG][BM][A_ST];     // 73728 B
    __half B[NSTG][BK][B2_ST];    // 135168 B
};                                // 208896 B

__device__ __forceinline__ void g2_load(SmemG2* s, int st, int k0,
                                        int e, int m_base, int n_base, int ptid) {
    const __half* arow = g_hh + ((size_t)e * TOK + m_base) * ID + k0;
    const __half* brow = g_wdh + ((size_t)e * ID + k0) * HD + n_base;
#pragma unroll
    for (int i = 0; i < 8; i++) {                 // A: 1024 chunks
        int idx = ptid + i * 128;
        int row = idx >> 3, c = idx & 7;
        cp16(saddr(&s->A[st][row][c * 8]), arow + (size_t)row * ID + c * 8);
    }
#pragma unroll
    for (int i = 0; i < 16; i++) {                // B: 64x32 = 2048 chunks
        int idx = ptid + i * 128;
        int kr = idx >> 5, c = idx & 31;
        cp16(saddr(&s->B[st][kr][c * 8]), brow + (size_t)kr * HD + c * 8);
    }
}

__global__ void __launch_bounds__(NTHR) gemm2_kernel() {
    extern __shared__ __align__(16) char smem_raw[];
    SmemG2* s = (SmemG2*)smem_raw;
    int tid = threadIdx.x;
    const int T = total_tiles(NT2);

    if (tid >= 256) {
        // ---------------- producer (4 warps) ----------------
        int ptid = tid - 256;
        int g = 0;
        for (int tile = blockIdx.x; tile < T; tile += gridDim.x) {
            int e, m_base, n_idx, cnt;
            decode_tile(tile, NT2, e, m_base, n_idx, cnt);
            int n_base = n_idx * BN2;
            for (int kt = 0; kt < KT2; kt++) {
                int sg = g & 3;
                if (g >= NSTG) bar_sync(5 + sg);               // EMPTY
                g2_load(s, sg, kt * BK, e, m_base, n_base, ptid);
                cp_commit();
                if (g >= 1) { cp_wait<1>(); bar_arrive(1 + ((g - 1) & 3)); }  // FULL
                g++;
            }
        }
        if (g >= 1) { cp_wait<0>(); bar_arrive(1 + ((g - 1) & 3)); }
        return;
    }

    // ---------------- consumer (8 warps) ----------------
    int wid = tid >> 5, lane = tid & 31;
    int wm = wid >> 2, wn = wid & 3;               // 2 x 4 warps, warp 64x64
    int r = lane >> 2, cq = lane & 3;
    int lrow = lane & 15, lcol = (lane >> 4) << 3;
    int g = 0;

    for (int tile = blockIdx.x; tile < T; tile += gridDim.x) {
        int e, m_base, n_idx, cnt;
        decode_tile(tile, NT2, e, m_base, n_idx, cnt);
        int n_base = n_idx * BN2;

        float acc[4][8][4];
#pragma unroll
        for (int mf = 0; mf < 4; mf++)
#pragma unroll
            for (int nf = 0; nf < 8; nf++)
#pragma unroll
                for (int k = 0; k < 4; k++) acc[mf][nf][k] = 0.f;

        for (int kt = 0; kt < KT2; kt++) {
            int sg = g & 3;
            bar_sync(1 + sg);                                 // FULL
            uint32_t sA = saddr(&s->A[sg][0][0]);
            uint32_t sB = saddr(&s->B[sg][0][0]);
#pragma unroll
            for (int ks = 0; ks < BK / 16; ks++) {
                int k16 = ks * 16;
                uint32_t a[4][4];
#pragma unroll
                for (int mf = 0; mf < 4; mf++)
                    ldsm_x4(a[mf], sA + 2 * ((wm * 64 + mf * 16 + lrow) * A_ST + k16 + lcol));
                uint32_t b[4][4];
#pragma unroll
                for (int ng = 0; ng < 4; ng++) {
                    uint32_t off = 2 * ((k16 + lrow) * B2_ST + wn * 64 + ng * 16 + lcol);
                    ldsm_x4t(b[ng], sB + off);
                }
#pragma unroll
                for (int mf = 0; mf < 4; mf++)
#pragma unroll
                    for (int nf = 0; nf < 8; nf++)
                        mma_f16(acc[mf][nf], a[mf], &b[nf >> 1][(nf & 1) * 2]);
            }
            bar_arrive(5 + sg);                               // EMPTY
            g++;
        }

        // epilogue: plain stores to g_y[k][t]
#pragma unroll
        for (int mf = 0; mf < 4; mf++) {
            int rl0 = wm * 64 + mf * 16 + r;
            int pk0 = (m_base + rl0 < cnt) ? g_tokp[e * TOK + m_base + rl0] : -1;
            int pk1 = (m_base + rl0 + 8 < cnt) ? g_tokp[e * TOK + m_base + rl0 + 8] : -1;
#pragma unroll
            for (int nf = 0; nf < 8; nf++) {
                int col = n_base + wn * 64 + nf * 8 + cq * 2;
                if (pk0 != -1) {
                    int t = pk0 & 0x7fffffff;
                    int k = (uint32_t)pk0 >> 31;
                    float2* p = (float2*)&g_y[((size_t)k * TOK + t) * HD + col];
                    *p = make_float2(acc[mf][nf][0], acc[mf][nf][1]);
                }
                if (pk1 != -1) {
                    int t = pk1 & 0x7fffffff;
                    int k = (uint32_t)pk1 >> 31;
                    float2* p = (float2*)&g_y[((size_t)k * TOK + t) * HD + col];
                    *p = make_float2(acc[mf][nf][2], acc[mf][nf][3]);
                }
            }
        }
    }
}

// ---------------- combine: out = w0*y0 + w1*y1 ----------------------------------
__global__ void combine_kernel(float4* __restrict__ out) {
    const int n4 = TOK * HD / 4;
    const float4* y0 = (const float4*)g_y;
    const float4* y1 = y0 + n4;
    for (int i = blockIdx.x * blockDim.x + threadIdx.x; i < n4; i += gridDim.x * blockDim.x) {
        int t = i / (HD / 4);
        float w0 = g_w2[2 * t], w1 = g_w2[2 * t + 1];
        float4 a = y0[i], b = y1[i];
        float4 o;
        o.x = w0 * a.x + w1 * b.x;
        o.y = w0 * a.y + w1 * b.y;
        o.z = w0 * a.z + w1 * b.z;
        o.w = w0 * a.w + w1 * b.w;
        out[i] = o;
    }
}

// ---------------- host launcher -------------------------------------------------
extern "C" void kernel_launch(void* const* d_in, const int* in_sizes, int n_in,
                              void* d_out, int out_size) {
    const float* x  = (const float*)d_in[0];
    const float* gw = (const float*)d_in[1];
    const float* wg = (const float*)d_in[2];
    const float* wu = (const float*)d_in[3];
    const float* wd = (const float*)d_in[4];
    (void)in_sizes; (void)n_in; (void)out_size;

    int nsm = 148;
    cudaDeviceGetAttribute(&nsm, cudaDevAttrMultiProcessorCount, 0);

    zero_cnt_kernel<<<1, 32>>>();

    {
        dim3 grid(1024, 1, 3);
        conv_half_kernel<<<grid, 256>>>((const float4*)wg, (const float4*)wu,
                                        (const float4*)wd);
    }

    cudaFuncSetAttribute(router_kernel, cudaFuncAttributeMaxDynamicSharedMemorySize,
                         NE * HD * (int)sizeof(float));
    router_kernel<<<TOK * 32 / 256, 256, NE * HD * sizeof(float)>>>(x, gw);

    cudaFuncSetAttribute(gemm1_kernel, cudaFuncAttributeMaxDynamicSharedMemorySize,
                         (int)sizeof(SmemG1));
    gemm1_kernel<<<nsm, NTHR, sizeof(SmemG1)>>>();

    cudaFuncSetAttribute(gemm2_kernel, cudaFuncAttributeMaxDynamicSharedMemorySize,
                         (int)sizeof(SmemG2));
    gemm2_kernel<<<nsm, NTHR, sizeof(SmemG2)>>>();

    combine_kernel<<<2048, 256>>>((float4*)d_out);
}